// round 13
// baseline (speedup 1.0000x reference)
#include <cuda_runtime.h>
#include <cuda_bf16.h>
#include <cstdint>
#include <cstdio>

// ---------------------------------------------------------------------------
// Problem constants
// ---------------------------------------------------------------------------
#define NB 1024
static const int D_TOT = 267696;

// permuted tf32 weight buffer offsets (see wperm_k); ICC per layer:
// {8,16,16,16,16,16,16,8,8,8,8,8,8,8,16,16,16,16,16}
static const int PO_H[19] = {0,1152,3584,6016,8448,10880,13312,15744,20352,29568,
                             38784,48000,57216,66432,84864,123776,162688,201600,240512};
#define WP_TOT 279424

__constant__ int c_PO[19]   = {0,1152,3584,6016,8448,10880,13312,15744,20352,29568,
                               38784,48000,57216,66432,84864,123776,162688,201600,240512};
__constant__ int c_WOFF[19] = {0,432,2736,5040,7344,9648,11952,14256,18864,28080,
                               37296,46512,55728,64944,83376,120240,157104,193968,230832};
__constant__ int c_LCIN[19]  = {3,16,16,16,16,16,16,16,32,32,32,32,32,32,64,64,64,64,64};
__constant__ int c_LICC[19]  = {8,16,16,16,16,16,16,8,8,8,8,8,8,8,16,16,16,16,16};
__constant__ int c_LCOUT[19] = {16,16,16,16,16,16,16,32,32,32,32,32,32,64,64,64,64,64,64};
__constant__ int c_LPITCH[19]= {72,152,152,152,152,152,152,72,72,72,72,72,72,72,152,152,152,152,152};

// ---------------------------------------------------------------------------
// Device scratch
// ---------------------------------------------------------------------------
#define BUF_ELEMS (1024*16*32*32)
__device__ float    g_bufA[BUF_ELEMS];
__device__ float    g_bufB[BUF_ELEMS];
__device__ float    g_bufC[BUF_ELEMS];
__device__ float    g_bufD[BUF_ELEMS];
__device__ float    g_w[267696];       // natural per-layer layout: [oc][ic][3][3]
__device__ uint32_t g_wp[WP_TOT];      // permuted tf32 smem-image weights
__device__ double   g_stats[19*64*2];  // per layer, per channel: sum, sumsq

// ---------------------------------------------------------------------------
// helpers
// ---------------------------------------------------------------------------
__host__ __device__ constexpr int pitchf(int K) {
    int p = K;
    while (!((p % 32) == 8 || (p % 32) == 24)) p++;
    return p;
}
__device__ __forceinline__ uint32_t f2tf32(float v) {
    uint32_t u; asm("cvt.rna.tf32.f32 %0, %1;" : "=r"(u) : "f"(v)); return u;
}
__device__ __forceinline__ void mma_tf32(float c[4],
                                         uint32_t a0, uint32_t a1, uint32_t a2, uint32_t a3,
                                         uint32_t b0, uint32_t b1) {
    asm volatile(
        "mma.sync.aligned.m16n8k8.row.col.f32.tf32.tf32.f32 "
        "{%0,%1,%2,%3}, {%4,%5,%6,%7}, {%8,%9}, {%0,%1,%2,%3};"
        : "+f"(c[0]), "+f"(c[1]), "+f"(c[2]), "+f"(c[3])
        : "r"(a0), "r"(a1), "r"(a2), "r"(a3), "r"(b0), "r"(b1));
}

// ---------------------------------------------------------------------------
__global__ void zstats_k(double* __restrict__ st) {
    int i = blockIdx.x * blockDim.x + threadIdx.x;
    if (i < 19*64*2) st[i] = 0.0;
}

__global__ void wbuild_k(const float* __restrict__ ow, const float* __restrict__ P,
                         const float* __restrict__ npar, float* __restrict__ wt) {
    __shared__ float s_np[40];
    if (threadIdx.x < 40) s_np[threadIdx.x] = npar[threadIdx.x];
    __syncthreads();
    int d = blockIdx.x * blockDim.x + threadIdx.x;
    if (d >= D_TOT) return;
    float a = ow[d];
#pragma unroll
    for (int j = 0; j < 40; j++)
        a = fmaf(s_np[j], P[(size_t)j * D_TOT + d], a);
    wt[d] = a;
}

// Permute weights into the exact smem image the conv consumes.
__global__ void wperm_k(const float* __restrict__ w, uint32_t* __restrict__ wp) {
    int i = blockIdx.x * blockDim.x + threadIdx.x;
    if (i >= WP_TOT) return;
    int l = 18;
    while (l > 0 && i < c_PO[l]) l--;
    const int r     = i - c_PO[l];
    const int CINR  = c_LCIN[l];
    const int ICC   = c_LICC[l];
    const int COUT  = c_LCOUT[l];
    const int PITCH = c_LPITCH[l];
    const int K     = ICC * 9;
    const int NG    = ICC / 8;
    const int cs    = COUT * PITCH;
    const int ch    = r / cs;
    const int r2    = r - ch * cs;
    const int oc    = r2 / PITCH;
    const int pos   = r2 - oc * PITCH;
    float v = 0.f;
    if (pos < K) {
        const int s    = pos >> 3, phys = pos & 7;
        const int u    = (phys & 1) ? (phys >> 1) + 4 : (phys >> 1);
        const int k    = s / NG, icg = s - (s / NG) * NG;
        const int ic   = ch * ICC + icg * 8 + u;
        if (ic < CINR) v = w[c_WOFF[l] + (oc * CINR + ic) * 9 + k];
    }
    wp[i] = f2tf32(v);
}

// Transpose NCHW 3-channel input to NHWC-8 (channels 3..7 zero).
__global__ void __launch_bounds__(256)
xpose_k(const float* __restrict__ in, float* __restrict__ out) {
    const int idx = blockIdx.x * 256 + threadIdx.x;   // (n*1024 + y*32 + x)
    const int n  = idx >> 10;
    const int hw = idx & 1023;
    const float* ib = in + (size_t)n * 3 * 1024 + hw;
    float4 a = make_float4(__ldg(ib), __ldg(ib + 1024), __ldg(ib + 2048), 0.f);
    float4 b = make_float4(0.f, 0.f, 0.f, 0.f);
    float4* ob = (float4*)(out + (size_t)idx * 8);
    ob[0] = a;
    ob[1] = b;
}

// ---------------------------------------------------------------------------
// Direct-from-tile tensor-core conv, channel-last activations.
//  WRES: stage ALL weight chunks into smem once before the mainloop.
//  MT = m16-tiles per warp; positions per CTA = 128*MT. MINB = min blocks/SM.
//  MODE 0: plain; 1: relu(bn(in)); 2: +identity prev; 3: +padded/strided prev.
//  WF: also write transformed activation to `fused` (channel-last).
// ---------------------------------------------------------------------------
template<int CINR, int CINP, int COUT, int HIN, int STRIDE, int ICC, int IMGS,
         int MT, int MODE, int CPREV, bool WF, int MINB, bool WRES>
__global__ void __launch_bounds__(256, MINB)
convt_k(const float* __restrict__ in, const uint32_t* __restrict__ wpb,
        float* __restrict__ out, const double* __restrict__ st_in,
        double* __restrict__ st_out, const float* __restrict__ prev,
        float* __restrict__ fused)
{
    constexpr int W     = HIN / STRIDE;
    constexpr int NPOS  = W * W;
    constexpr int PC    = 128 * MT;              // positions per CTA
    constexpr int R     = PC / (W * IMGS);
    constexpr int SPI   = (IMGS == 1) ? (NPOS / PC) : 1;
    constexpr int TH    = (R - 1) * STRIDE + 3;
    constexpr int TW    = HIN + 2;
    constexpr int NG    = ICC / 8;
    constexpr int NCH   = CINP / ICC;
    constexpr int K     = ICC * 9;
    constexpr int PITCH = pitchf(K);
    constexpr int STEPS = K / 8;
    constexpr int NC    = COUT / 8;
    constexpr int TILEW = IMGS * TH * TW * ICC;
    constexpr int PADF  = (MODE == 3) ? (CINR - CPREV) / 2 : 0;
    constexpr int WCH   = WRES ? NCH : 1;        // weight chunks held in smem

    extern __shared__ float smf[];
    float*    s_sc = smf;
    float*    s_sh = smf + 64;
    uint32_t* s_a  = (uint32_t*)(smf + 128);
    uint32_t* s_b  = s_a + TILEW;

    const int tid = threadIdx.x, wid = tid >> 5, lane = tid & 31;
    const int g = lane >> 2, t = lane & 3;

    const int img0 = (IMGS == 1) ? (blockIdx.x / SPI) : blockIdx.x * IMGS;
    const int r0   = (IMGS == 1) ? (blockIdx.x % SPI) * R : 0;

    if (MODE >= 1 && tid < CINR) {
        const double cnt = 1024.0 * HIN * HIN;
        double mm = st_in[tid*2]   / cnt;
        double vv = st_in[tid*2+1] / cnt - mm * mm;
        float rs = rsqrtf((float)vv + 1e-5f);
        s_sc[tid] = rs;
        s_sh[tid] = (float)(-mm) * rs;
    }

    // WRES: stage all weight chunks once (no sync needed yet; sync below covers)
    if (WRES) {
        const uint4* wb = (const uint4*)wpb;
        uint4* sb4 = (uint4*)s_b;
#pragma unroll 4
        for (int idx = tid; idx < NCH * COUT * PITCH / 4; idx += 256)
            sb4[idx] = wb[idx];
    }
    if (MODE >= 1 || WRES) __syncthreads();

    // row-base word offsets into the tile (rows g, g+8, ... per m16 tile)
    int basew[2 * MT];
#pragma unroll
    for (int i = 0; i < 2 * MT; i++) {
        const int p   = wid * (16 * MT) + i * 8 + g;
        const int img = p / (R * W);
        const int rem = p - img * (R * W);
        const int y   = rem / W, x = rem - (rem / W) * W;
        basew[i] = (((img * TH + y * STRIDE) * NG) * TW + x * STRIDE) * 8 + 2 * t;
    }

    float acc[MT][NC][4];
#pragma unroll
    for (int mt = 0; mt < MT; mt++)
#pragma unroll
        for (int nc = 0; nc < NC; nc++)
#pragma unroll
            for (int i = 0; i < 4; i++) acc[mt][nc][i] = 0.f;

    for (int ch = 0; ch < NCH; ch++) {
        const int ic0 = ch * ICC;
        __syncthreads();

        // ---- stage input tile: phase-1 batch loads, phase-2 transform+store ----
        for (int idx = tid; idx < IMGS * TH * TW; idx += 256) {
            const int img = idx / (TH * TW);
            const int rr  = idx - img * (TH * TW);
            const int ty  = rr / TW, tx = rr - (rr / TW) * TW;
            const int yi  = r0 * STRIDE - 1 + ty;
            const int xi  = tx - 1;
            const bool ok = (unsigned)yi < (unsigned)HIN && (unsigned)xi < (unsigned)HIN;
            const int  n  = img0 + img;
            uint32_t* dst = s_a + ((img * TH + ty) * NG) * (TW * 8) + tx * 8;

            const float* gcl = in + (((size_t)n * HIN + yi) * HIN + xi) * CINR + ic0;
            const float* pcl = nullptr;
            if (MODE == 2)
                pcl = prev + (((size_t)n * HIN + yi) * HIN + xi) * CPREV + ic0;
            if (MODE == 3)
                pcl = prev + (((size_t)n * (2*HIN) + 2*yi) * (2*HIN) + 2*xi) * CPREV
                           + (ic0 - PADF);
            float* fcl = nullptr;
            if (WF) fcl = fused + (((size_t)n * HIN + yi) * HIN + xi) * CINR + ic0;

            // phase 1: issue all loads (input + shortcut) concurrently
            float4 ia[NG][2], pa[NG][2];
#pragma unroll
            for (int icg = 0; icg < NG; icg++) {
                if (ok) {
                    ia[icg][0] = *(const float4*)(gcl + icg * 8);
                    ia[icg][1] = *(const float4*)(gcl + icg * 8 + 4);
                } else {
                    ia[icg][0] = make_float4(0.f,0.f,0.f,0.f);
                    ia[icg][1] = make_float4(0.f,0.f,0.f,0.f);
                }
            }
            if (MODE == 2 || MODE == 3) {
#pragma unroll
                for (int icg = 0; icg < NG; icg++) {
                    bool pv = ok;
                    if (MODE == 3) {
                        const int gic0 = ic0 + icg * 8 - PADF;
                        pv = ok && (gic0 >= 0) && (gic0 + 8 <= CPREV);
                    }
                    if (pv) {
                        pa[icg][0] = *(const float4*)(pcl + icg * 8);
                        pa[icg][1] = *(const float4*)(pcl + icg * 8 + 4);
                    } else {
                        pa[icg][0] = make_float4(0.f,0.f,0.f,0.f);
                        pa[icg][1] = make_float4(0.f,0.f,0.f,0.f);
                    }
                }
            }

            // phase 2: transform + store
#pragma unroll
            for (int icg = 0; icg < NG; icg++) {
                float4 a4 = ia[icg][0], b4 = ia[icg][1];
                if (MODE >= 1 && ok) {
                    const float4 sa = *(const float4*)&s_sc[ic0 + icg*8];
                    const float4 sb = *(const float4*)&s_sc[ic0 + icg*8 + 4];
                    const float4 ha = *(const float4*)&s_sh[ic0 + icg*8];
                    const float4 hb = *(const float4*)&s_sh[ic0 + icg*8 + 4];
                    a4.x = fmaf(a4.x, sa.x, ha.x); a4.y = fmaf(a4.y, sa.y, ha.y);
                    a4.z = fmaf(a4.z, sa.z, ha.z); a4.w = fmaf(a4.w, sa.w, ha.w);
                    b4.x = fmaf(b4.x, sb.x, hb.x); b4.y = fmaf(b4.y, sb.y, hb.y);
                    b4.z = fmaf(b4.z, sb.z, hb.z); b4.w = fmaf(b4.w, sb.w, hb.w);
                    if (MODE >= 2) {
                        a4.x += pa[icg][0].x; a4.y += pa[icg][0].y;
                        a4.z += pa[icg][0].z; a4.w += pa[icg][0].w;
                        b4.x += pa[icg][1].x; b4.y += pa[icg][1].y;
                        b4.z += pa[icg][1].z; b4.w += pa[icg][1].w;
                    }
                    a4.x = fmaxf(a4.x, 0.f); a4.y = fmaxf(a4.y, 0.f);
                    a4.z = fmaxf(a4.z, 0.f); a4.w = fmaxf(a4.w, 0.f);
                    b4.x = fmaxf(b4.x, 0.f); b4.y = fmaxf(b4.y, 0.f);
                    b4.z = fmaxf(b4.z, 0.f); b4.w = fmaxf(b4.w, 0.f);
                }
                if (WF && ok) {
                    *(float4*)(fcl + icg * 8)     = a4;
                    *(float4*)(fcl + icg * 8 + 4) = b4;
                }
                // permute to fragment order: (a.x,b.x,a.y,b.y,a.z,b.z,a.w,b.w)
                uint4* d4 = (uint4*)(dst + icg * (TW * 8));
                d4[0] = make_uint4(f2tf32(a4.x), f2tf32(b4.x),
                                   f2tf32(a4.y), f2tf32(b4.y));
                d4[1] = make_uint4(f2tf32(a4.z), f2tf32(b4.z),
                                   f2tf32(a4.w), f2tf32(b4.w));
            }
        }

        // ---- stage B per chunk (skipped when weights resident) ----
        if (!WRES) {
            const uint4* wb = (const uint4*)(wpb + ch * (COUT * PITCH));
            uint4* sb4 = (uint4*)s_b;
#pragma unroll 4
            for (int idx = tid; idx < COUT * PITCH / 4; idx += 256)
                sb4[idx] = wb[idx];
        }
        __syncthreads();

        // ---- MMA over STEPS k-slices ----
        const uint32_t* bch = s_b + (WRES ? ch * (COUT * PITCH) : 0);
#pragma unroll
        for (int s = 0; s < STEPS; s++) {
            const int k   = s / NG;
            const int icg = s - k * NG;
            const int ky  = k / 3, kx = k - (k / 3) * 3;
            const int off = ((ky * NG + icg) * TW + kx) * 8;
            uint2 Af[2 * MT];
#pragma unroll
            for (int i = 0; i < 2 * MT; i++)
                Af[i] = *(const uint2*)(s_a + basew[i] + off);
#pragma unroll
            for (int nc = 0; nc < NC; nc++) {
                uint2 B = *(const uint2*)(bch + (nc * 8 + g) * PITCH + s * 8 + 2 * t);
#pragma unroll
                for (int mt = 0; mt < MT; mt++)
                    mma_tf32(acc[mt][nc], Af[2*mt].x, Af[2*mt+1].x,
                             Af[2*mt].y, Af[2*mt+1].y, B.x, B.y);
            }
        }
    }

    __syncthreads();   // mainloop smem regions free from here
    float* s_st  = smf + 128;          // [PC][COUT]
    float* s_red = s_st + COUT * PC;   // [8 warps][COUT][2]

    // ---- BN stats straight from accumulators ----
#pragma unroll
    for (int nc = 0; nc < NC; nc++) {
        float s0 = 0.f, s1 = 0.f, q0 = 0.f, q1 = 0.f;
#pragma unroll
        for (int mt = 0; mt < MT; mt++) {
            s0 += acc[mt][nc][0] + acc[mt][nc][2];
            s1 += acc[mt][nc][1] + acc[mt][nc][3];
            q0 += acc[mt][nc][0]*acc[mt][nc][0] + acc[mt][nc][2]*acc[mt][nc][2];
            q1 += acc[mt][nc][1]*acc[mt][nc][1] + acc[mt][nc][3]*acc[mt][nc][3];
        }
#pragma unroll
        for (int off = 4; off < 32; off <<= 1) {
            s0 += __shfl_xor_sync(0xffffffffu, s0, off);
            s1 += __shfl_xor_sync(0xffffffffu, s1, off);
            q0 += __shfl_xor_sync(0xffffffffu, q0, off);
            q1 += __shfl_xor_sync(0xffffffffu, q1, off);
        }
        if (lane < 4) {
            const int cb = nc * 8 + 2 * lane;
            s_red[(wid * COUT + cb)     * 2 + 0] = s0;
            s_red[(wid * COUT + cb)     * 2 + 1] = q0;
            s_red[(wid * COUT + cb + 1) * 2 + 0] = s1;
            s_red[(wid * COUT + cb + 1) * 2 + 1] = q1;
        }
    }

    // ---- frags -> smem staging [PC][COUT] (float2 per frag pair) ----
#pragma unroll
    for (int mt = 0; mt < MT; mt++)
#pragma unroll
        for (int nc = 0; nc < NC; nc++) {
            const int cb = nc * 8 + 2 * t;
            const int p0 = wid * (16 * MT) + mt * 16 + g;
            *(float2*)&s_st[p0 * COUT + cb]       = make_float2(acc[mt][nc][0], acc[mt][nc][1]);
            *(float2*)&s_st[(p0 + 8) * COUT + cb] = make_float2(acc[mt][nc][2], acc[mt][nc][3]);
        }
    __syncthreads();

    // coalesced channel-last store (float4)
    for (int idx = tid; idx < COUT * PC / 4; idx += 256) {
        const int c4  = idx % (COUT / 4);
        const int lp  = idx / (COUT / 4);
        const int img = lp / (R * W);
        const int rem = lp - img * (R * W);
        const int y   = r0 + rem / W;
        const int x   = rem - (rem / W) * W;
        const float4 v = *(const float4*)&s_st[lp * COUT + c4 * 4];
        *(float4*)&out[(((size_t)(img0 + img) * W + y) * W + x) * COUT + c4 * 4] = v;
    }

    if (tid < COUT) {
        float s = 0.f, q = 0.f;
#pragma unroll
        for (int w8 = 0; w8 < 8; w8++) {
            s += s_red[(w8 * COUT + tid) * 2 + 0];
            q += s_red[(w8 * COUT + tid) * 2 + 1];
        }
        atomicAdd(&st_out[tid * 2 + 0], (double)s);
        atomicAdd(&st_out[tid * 2 + 1], (double)q);
    }
}

// ---------------------------------------------------------------------------
// Fused final residual + global average pool (8x8) + FC 64->10 (channel-last)
// ---------------------------------------------------------------------------
__global__ void __launch_bounds__(64)
poolfc_k(const float* __restrict__ h2, const double* __restrict__ st,
         const float* __restrict__ prev, const float* __restrict__ Wfc,
         const float* __restrict__ bfc, float* __restrict__ out)
{
    __shared__ float pooled[64];
    const int n = blockIdx.x, t = threadIdx.x;
    const double cnt = 1024.0 * 64.0;
    double m = st[t*2] / cnt;
    double v = st[t*2+1] / cnt - m * m;
    const float sc = rsqrtf((float)v + 1e-5f);
    const float sh = (float)(-m) * sc;
    const float* hp = h2   + (size_t)n * 64 * 64;
    const float* pp = prev + (size_t)n * 64 * 64;
    float s = 0.f;
#pragma unroll
    for (int i = 0; i < 64; i++)
        s += fmaxf(fmaf(hp[i * 64 + t], sc, sh) + pp[i * 64 + t], 0.f);
    pooled[t] = s * (1.f / 64.f);
    __syncthreads();
    if (t < 10) {
        float a = bfc[t];
#pragma unroll
        for (int c = 0; c < 64; c++) a = fmaf(Wfc[t * 64 + c], pooled[c], a);
        out[n * 10 + t] = a;
    }
}

// ---------------------------------------------------------------------------
// Host-side smem size (mirror of kernel constants)
// ---------------------------------------------------------------------------
static constexpr int cm2(int CINP, int COUT, int HIN, int STRIDE, int ICC,
                         int IMGS, int MT, bool WRES) {
    int W  = HIN / STRIDE;
    int PC = 128 * MT;
    int R  = PC / (W * IMGS);
    int TH = (R - 1) * STRIDE + 3;
    int TW = HIN + 2;
    int K  = ICC * 9;
    int P  = pitchf(K);
    int NCH = CINP / ICC;
    int tile = IMGS * TH * TW * ICC;
    int p1 = tile + (WRES ? NCH : 1) * COUT * P;
    int p2 = COUT * PC + 16 * COUT;
    int m  = (p1 > p2) ? p1 : p2;
    return (128 + m) * 4;
}

extern "C" void kernel_launch(void* const* d_in, const int* in_sizes, int n_in,
                              void* d_out, int out_size)
{
    (void)in_sizes; (void)n_in; (void)out_size;
    const float* x   = (const float*)d_in[0];
    const float* ow  = (const float*)d_in[1];
    const float* P   = (const float*)d_in[2];
    const float* npar= (const float*)d_in[3];
    const float* Wfc = (const float*)d_in[4];
    const float* bfc = (const float*)d_in[5];
    float* y = (float*)d_out;

    float *A, *B, *C, *D, *w; uint32_t* wp; double* st;
    cudaGetSymbolAddress((void**)&A,  g_bufA);
    cudaGetSymbolAddress((void**)&B,  g_bufB);
    cudaGetSymbolAddress((void**)&C,  g_bufC);
    cudaGetSymbolAddress((void**)&D,  g_bufD);
    cudaGetSymbolAddress((void**)&w,  g_w);
    cudaGetSymbolAddress((void**)&wp, g_wp);
    cudaGetSymbolAddress((void**)&st, g_stats);

    #define SETSM(FN, CINP_, COUT_, HIN_, STRIDE_, ICC_, IMGS_, MT_, WRES_) \
        cudaFuncSetAttribute(FN, cudaFuncAttributeMaxDynamicSharedMemorySize, \
                             cm2(CINP_, COUT_, HIN_, STRIDE_, ICC_, IMGS_, MT_, WRES_))

    // 16-ch variants: MINB=6 (75% occ); 32-out: MINB=4 + WRES; 64-out: MINB=2
    auto I0  = convt_k< 8, 8,16,32,1, 8,1,2,0, 0,false,6,false>; SETSM(I0,  8,16,32,1, 8,1,2,false);
    auto I1  = convt_k<16,16,16,32,1,16,1,2,1, 0,true ,6,false>; SETSM(I1, 16,16,32,1,16,1,2,false);
    auto I2  = convt_k<16,16,16,32,1,16,1,2,1, 0,false,6,false>; SETSM(I2, 16,16,32,1,16,1,2,false);
    auto I3  = convt_k<16,16,16,32,1,16,1,2,2,16,true ,6,false>; SETSM(I3, 16,16,32,1,16,1,2,false);
    auto I4  = convt_k<16,16,32,32,2, 8,1,2,2,16,true ,4,true >; SETSM(I4, 16,32,32,2, 8,1,2,true);
    auto I5  = convt_k<32,32,32,16,1, 8,1,2,1, 0,false,4,true >; SETSM(I5, 32,32,16,1, 8,1,2,true);
    auto I6  = convt_k<32,32,32,16,1, 8,1,2,3,16,true ,4,true >; SETSM(I6, 32,32,16,1, 8,1,2,true);
    auto I7  = convt_k<32,32,32,16,1, 8,1,2,2,32,true ,4,true >; SETSM(I7, 32,32,16,1, 8,1,2,true);
    auto I8  = convt_k<32,32,64,16,2, 8,4,2,2,32,true ,2,false>; SETSM(I8, 32,64,16,2, 8,4,2,false);
    auto I9  = convt_k<64,64,64, 8,1,16,4,2,1, 0,false,2,false>; SETSM(I9, 64,64, 8,1,16,4,2,false);
    auto I10 = convt_k<64,64,64, 8,1,16,4,2,3,32,true ,2,false>; SETSM(I10,64,64, 8,1,16,4,2,false);
    auto I11 = convt_k<64,64,64, 8,1,16,4,2,2,64,true ,2,false>; SETSM(I11,64,64, 8,1,16,4,2,false);
    #undef SETSM

    auto ST = [&](int l) { return st + l * 128; };
    auto WL = [&](int l) { return wp + PO_H[l]; };

    zstats_k<<<(19*64*2 + 255)/256, 256>>>(st);
    wbuild_k<<<(D_TOT + 255)/256, 256>>>(ow, P, npar, w);
    wperm_k<<<(WP_TOT + 255)/256, 256>>>(w, wp);
    xpose_k<<<4096, 256>>>(x, D);   // NCHW 3ch -> NHWC-8 (zero padded)

    const int S1 = cm2( 8,16,32,1, 8,1,2,false);
    const int S2 = cm2(16,16,32,1,16,1,2,false);
    const int S3 = cm2(16,32,32,2, 8,1,2,true);
    const int S4 = cm2(32,32,16,1, 8,1,2,true);
    const int S5 = cm2(32,64,16,2, 8,4,2,false);
    const int S6 = cm2(64,64, 8,1,16,4,2,false);

    // layer 0 (channel-last padded input in D)
    I0 <<<4096,256,S1>>>(D, WL(0), A, nullptr, ST(0), nullptr, nullptr);
    // block 1
    I1 <<<4096,256,S2>>>(A, WL(1), B, ST(0),  ST(1), nullptr, C);
    I2 <<<4096,256,S2>>>(B, WL(2), A, ST(1),  ST(2), nullptr, nullptr);
    // block 2
    I3 <<<4096,256,S2>>>(A, WL(3), B, ST(2),  ST(3), C, D);
    I2 <<<4096,256,S2>>>(B, WL(4), C, ST(3),  ST(4), nullptr, nullptr);
    // block 3
    I3 <<<4096,256,S2>>>(C, WL(5), B, ST(4),  ST(5), D, A);
    I2 <<<4096,256,S2>>>(B, WL(6), D, ST(5),  ST(6), nullptr, nullptr);
    // block 4 (16->32, stride 2)
    I4 <<<1024,256,S3>>>(D, WL(7), B, ST(6),  ST(7), A, C);
    I5 <<<1024,256,S4>>>(B, WL(8), A, ST(7),  ST(8), nullptr, nullptr);
    // block 5 (MODE3 pad shortcut, prev 16ch@32)
    I6 <<<1024,256,S4>>>(A, WL(9), B, ST(8),  ST(9), C, D);
    I5 <<<1024,256,S4>>>(B, WL(10),C, ST(9),  ST(10),nullptr, nullptr);
    // block 6
    I7 <<<1024,256,S4>>>(C, WL(11),B, ST(10), ST(11),D, A);
    I5 <<<1024,256,S4>>>(B, WL(12),D, ST(11), ST(12),nullptr, nullptr);
    // block 7 (32->64, stride 2)
    I8 <<< 256,256,S5>>>(D, WL(13),B, ST(12), ST(13),A, C);
    I9 <<< 256,256,S6>>>(B, WL(14),A, ST(13), ST(14),nullptr, nullptr);
    // block 8 (MODE3 pad shortcut, prev 32ch@16)
    I10<<< 256,256,S6>>>(A, WL(15),B, ST(14), ST(15),C, D);
    I9 <<< 256,256,S6>>>(B, WL(16),C, ST(15), ST(16),nullptr, nullptr);
    // block 9
    I11<<< 256,256,S6>>>(C, WL(17),B, ST(16), ST(17),D, A);
    I9 <<< 256,256,S6>>>(B, WL(18),D, ST(17), ST(18),nullptr, nullptr);
    // fused final residual + pool + fc
    poolfc_k<<<NB,64>>>(D, ST(18), A, Wfc, bfc, y);
}

// round 14
// speedup vs baseline: 1.0180x; 1.0180x over previous
#include <cuda_runtime.h>
#include <cuda_bf16.h>
#include <cstdint>
#include <cstdio>

// ---------------------------------------------------------------------------
// Problem constants
// ---------------------------------------------------------------------------
#define NB 1024
static const int D_TOT = 267696;

// permuted tf32 weight buffer offsets (see wperm_k); ICC per layer:
// {8,16,16,16,16,16,16,8,8,8,8,8,8,8,16,16,16,16,16}
static const int PO_H[19] = {0,1152,3584,6016,8448,10880,13312,15744,20352,29568,
                             38784,48000,57216,66432,84864,123776,162688,201600,240512};
#define WP_TOT 279424

__constant__ int c_PO[19]   = {0,1152,3584,6016,8448,10880,13312,15744,20352,29568,
                               38784,48000,57216,66432,84864,123776,162688,201600,240512};
__constant__ int c_WOFF[19] = {0,432,2736,5040,7344,9648,11952,14256,18864,28080,
                               37296,46512,55728,64944,83376,120240,157104,193968,230832};
__constant__ int c_LCIN[19]  = {3,16,16,16,16,16,16,16,32,32,32,32,32,32,64,64,64,64,64};
__constant__ int c_LICC[19]  = {8,16,16,16,16,16,16,8,8,8,8,8,8,8,16,16,16,16,16};
__constant__ int c_LCOUT[19] = {16,16,16,16,16,16,16,32,32,32,32,32,32,64,64,64,64,64,64};
__constant__ int c_LPITCH[19]= {72,152,152,152,152,152,152,72,72,72,72,72,72,72,152,152,152,152,152};

// ---------------------------------------------------------------------------
// Device scratch
// ---------------------------------------------------------------------------
#define BUF_ELEMS (1024*16*32*32)
__device__ float    g_bufA[BUF_ELEMS];
__device__ float    g_bufB[BUF_ELEMS];
__device__ float    g_bufC[BUF_ELEMS];
__device__ float    g_bufD[BUF_ELEMS];
__device__ float    g_w[267696];       // natural per-layer layout: [oc][ic][3][3]
__device__ uint32_t g_wp[WP_TOT];      // permuted tf32 smem-image weights
__device__ double   g_stats[19*64*2];  // per layer, per channel: sum, sumsq

// ---------------------------------------------------------------------------
// helpers
// ---------------------------------------------------------------------------
__host__ __device__ constexpr int pitchf(int K) {
    int p = K;
    while (!((p % 32) == 8 || (p % 32) == 24)) p++;
    return p;
}
__device__ __forceinline__ uint32_t f2tf32(float v) {
    uint32_t u; asm("cvt.rna.tf32.f32 %0, %1;" : "=r"(u) : "f"(v)); return u;
}
__device__ __forceinline__ void mma_tf32(float c[4],
                                         uint32_t a0, uint32_t a1, uint32_t a2, uint32_t a3,
                                         uint32_t b0, uint32_t b1) {
    asm volatile(
        "mma.sync.aligned.m16n8k8.row.col.f32.tf32.tf32.f32 "
        "{%0,%1,%2,%3}, {%4,%5,%6,%7}, {%8,%9}, {%0,%1,%2,%3};"
        : "+f"(c[0]), "+f"(c[1]), "+f"(c[2]), "+f"(c[3])
        : "r"(a0), "r"(a1), "r"(a2), "r"(a3), "r"(b0), "r"(b1));
}

// ---------------------------------------------------------------------------
__global__ void zstats_k(double* __restrict__ st) {
    int i = blockIdx.x * blockDim.x + threadIdx.x;
    if (i < 19*64*2) st[i] = 0.0;
}

__global__ void wbuild_k(const float* __restrict__ ow, const float* __restrict__ P,
                         const float* __restrict__ npar, float* __restrict__ wt) {
    __shared__ float s_np[40];
    if (threadIdx.x < 40) s_np[threadIdx.x] = npar[threadIdx.x];
    __syncthreads();
    int d = blockIdx.x * blockDim.x + threadIdx.x;
    if (d >= D_TOT) return;
    float a = ow[d];
#pragma unroll
    for (int j = 0; j < 40; j++)
        a = fmaf(s_np[j], P[(size_t)j * D_TOT + d], a);
    wt[d] = a;
}

// Permute weights into the exact smem image the conv consumes.
__global__ void wperm_k(const float* __restrict__ w, uint32_t* __restrict__ wp) {
    int i = blockIdx.x * blockDim.x + threadIdx.x;
    if (i >= WP_TOT) return;
    int l = 18;
    while (l > 0 && i < c_PO[l]) l--;
    const int r     = i - c_PO[l];
    const int CINR  = c_LCIN[l];
    const int ICC   = c_LICC[l];
    const int COUT  = c_LCOUT[l];
    const int PITCH = c_LPITCH[l];
    const int K     = ICC * 9;
    const int NG    = ICC / 8;
    const int cs    = COUT * PITCH;
    const int ch    = r / cs;
    const int r2    = r - ch * cs;
    const int oc    = r2 / PITCH;
    const int pos   = r2 - oc * PITCH;
    float v = 0.f;
    if (pos < K) {
        const int s    = pos >> 3, phys = pos & 7;
        const int u    = (phys & 1) ? (phys >> 1) + 4 : (phys >> 1);
        const int k    = s / NG, icg = s - (s / NG) * NG;
        const int ic   = ch * ICC + icg * 8 + u;
        if (ic < CINR) v = w[c_WOFF[l] + (oc * CINR + ic) * 9 + k];
    }
    wp[i] = f2tf32(v);
}

// Transpose NCHW 3-channel input to NHWC-8 (channels 3..7 zero).
__global__ void __launch_bounds__(256)
xpose_k(const float* __restrict__ in, float* __restrict__ out) {
    const int idx = blockIdx.x * 256 + threadIdx.x;   // (n*1024 + y*32 + x)
    const int n  = idx >> 10;
    const int hw = idx & 1023;
    const float* ib = in + (size_t)n * 3 * 1024 + hw;
    float4 a = make_float4(__ldg(ib), __ldg(ib + 1024), __ldg(ib + 2048), 0.f);
    float4 b = make_float4(0.f, 0.f, 0.f, 0.f);
    float4* ob = (float4*)(out + (size_t)idx * 8);
    ob[0] = a;
    ob[1] = b;
}

// ---------------------------------------------------------------------------
// Direct-from-tile tensor-core conv, channel-last activations.
//  Single-phase staging (low register pressure -> high occupancy via MINB).
//  MT = m16-tiles per warp; positions per CTA = 128*MT. MINB = min blocks/SM.
//  MODE 0: plain; 1: relu(bn(in)); 2: +identity prev; 3: +padded/strided prev.
//  WF: also write transformed activation to `fused` (channel-last).
// ---------------------------------------------------------------------------
template<int CINR, int CINP, int COUT, int HIN, int STRIDE, int ICC, int IMGS,
         int MT, int MODE, int CPREV, bool WF, int MINB>
__global__ void __launch_bounds__(256, MINB)
convt_k(const float* __restrict__ in, const uint32_t* __restrict__ wpb,
        float* __restrict__ out, const double* __restrict__ st_in,
        double* __restrict__ st_out, const float* __restrict__ prev,
        float* __restrict__ fused)
{
    constexpr int W     = HIN / STRIDE;
    constexpr int NPOS  = W * W;
    constexpr int PC    = 128 * MT;              // positions per CTA
    constexpr int R     = PC / (W * IMGS);
    constexpr int SPI   = (IMGS == 1) ? (NPOS / PC) : 1;
    constexpr int TH    = (R - 1) * STRIDE + 3;
    constexpr int TW    = HIN + 2;
    constexpr int NG    = ICC / 8;
    constexpr int NCH   = CINP / ICC;
    constexpr int K     = ICC * 9;
    constexpr int PITCH = pitchf(K);
    constexpr int STEPS = K / 8;
    constexpr int NC    = COUT / 8;
    constexpr int TILEW = IMGS * TH * TW * ICC;
    constexpr int PADF  = (MODE == 3) ? (CINR - CPREV) / 2 : 0;

    extern __shared__ float smf[];
    float*    s_sc = smf;
    float*    s_sh = smf + 64;
    uint32_t* s_a  = (uint32_t*)(smf + 128);
    uint32_t* s_b  = s_a + TILEW;

    const int tid = threadIdx.x, wid = tid >> 5, lane = tid & 31;
    const int g = lane >> 2, t = lane & 3;

    const int img0 = (IMGS == 1) ? (blockIdx.x / SPI) : blockIdx.x * IMGS;
    const int r0   = (IMGS == 1) ? (blockIdx.x % SPI) * R : 0;

    if (MODE >= 1 && tid < CINR) {
        const double cnt = 1024.0 * HIN * HIN;
        double mm = st_in[tid*2]   / cnt;
        double vv = st_in[tid*2+1] / cnt - mm * mm;
        float rs = rsqrtf((float)vv + 1e-5f);
        s_sc[tid] = rs;
        s_sh[tid] = (float)(-mm) * rs;
    }
    if (MODE >= 1) __syncthreads();

    // row-base word offsets into the tile (rows g, g+8, ... per m16 tile)
    int basew[2 * MT];
#pragma unroll
    for (int i = 0; i < 2 * MT; i++) {
        const int p   = wid * (16 * MT) + i * 8 + g;
        const int img = p / (R * W);
        const int rem = p - img * (R * W);
        const int y   = rem / W, x = rem - (rem / W) * W;
        basew[i] = (((img * TH + y * STRIDE) * NG) * TW + x * STRIDE) * 8 + 2 * t;
    }

    float acc[MT][NC][4];
#pragma unroll
    for (int mt = 0; mt < MT; mt++)
#pragma unroll
        for (int nc = 0; nc < NC; nc++)
#pragma unroll
            for (int i = 0; i < 4; i++) acc[mt][nc][i] = 0.f;

    for (int ch = 0; ch < NCH; ch++) {
        const int ic0 = ch * ICC;
        __syncthreads();

        // ---- stage input tile (single-phase: load, transform, store) ----
        for (int idx = tid; idx < IMGS * TH * TW; idx += 256) {
            const int img = idx / (TH * TW);
            const int rr  = idx - img * (TH * TW);
            const int ty  = rr / TW, tx = rr - (rr / TW) * TW;
            const int yi  = r0 * STRIDE - 1 + ty;
            const int xi  = tx - 1;
            const bool ok = (unsigned)yi < (unsigned)HIN && (unsigned)xi < (unsigned)HIN;
            const int  n  = img0 + img;
            uint32_t* dst = s_a + ((img * TH + ty) * NG) * (TW * 8) + tx * 8;

            const float* gcl = in + (((size_t)n * HIN + yi) * HIN + xi) * CINR + ic0;
            const float* pcl = nullptr;
            if (MODE == 2)
                pcl = prev + (((size_t)n * HIN + yi) * HIN + xi) * CPREV + ic0;
            if (MODE == 3)
                pcl = prev + (((size_t)n * (2*HIN) + 2*yi) * (2*HIN) + 2*xi) * CPREV
                           + (ic0 - PADF);
            float* fcl = nullptr;
            if (WF) fcl = fused + (((size_t)n * HIN + yi) * HIN + xi) * CINR + ic0;

#pragma unroll
            for (int icg = 0; icg < NG; icg++) {
                float4 a4 = make_float4(0.f,0.f,0.f,0.f);
                float4 b4 = make_float4(0.f,0.f,0.f,0.f);
                if (ok) {
                    a4 = *(const float4*)(gcl + icg * 8);
                    b4 = *(const float4*)(gcl + icg * 8 + 4);
                    if (MODE >= 1) {
                        const float4 sa = *(const float4*)&s_sc[ic0 + icg*8];
                        const float4 sb = *(const float4*)&s_sc[ic0 + icg*8 + 4];
                        const float4 ha = *(const float4*)&s_sh[ic0 + icg*8];
                        const float4 hb = *(const float4*)&s_sh[ic0 + icg*8 + 4];
                        a4.x = fmaf(a4.x, sa.x, ha.x); a4.y = fmaf(a4.y, sa.y, ha.y);
                        a4.z = fmaf(a4.z, sa.z, ha.z); a4.w = fmaf(a4.w, sa.w, ha.w);
                        b4.x = fmaf(b4.x, sb.x, hb.x); b4.y = fmaf(b4.y, sb.y, hb.y);
                        b4.z = fmaf(b4.z, sb.z, hb.z); b4.w = fmaf(b4.w, sb.w, hb.w);
                    }
                    if (MODE == 2) {
                        const float4 pa = *(const float4*)(pcl + icg * 8);
                        const float4 pb = *(const float4*)(pcl + icg * 8 + 4);
                        a4.x += pa.x; a4.y += pa.y; a4.z += pa.z; a4.w += pa.w;
                        b4.x += pb.x; b4.y += pb.y; b4.z += pb.z; b4.w += pb.w;
                    }
                    if (MODE == 3) {
                        const int gic0 = ic0 + icg * 8 - PADF;
                        if (gic0 >= 0 && gic0 + 8 <= CPREV) {
                            const float4 pa = *(const float4*)(pcl + icg * 8);
                            const float4 pb = *(const float4*)(pcl + icg * 8 + 4);
                            a4.x += pa.x; a4.y += pa.y; a4.z += pa.z; a4.w += pa.w;
                            b4.x += pb.x; b4.y += pb.y; b4.z += pb.z; b4.w += pb.w;
                        }
                    }
                    if (MODE >= 1) {
                        a4.x = fmaxf(a4.x, 0.f); a4.y = fmaxf(a4.y, 0.f);
                        a4.z = fmaxf(a4.z, 0.f); a4.w = fmaxf(a4.w, 0.f);
                        b4.x = fmaxf(b4.x, 0.f); b4.y = fmaxf(b4.y, 0.f);
                        b4.z = fmaxf(b4.z, 0.f); b4.w = fmaxf(b4.w, 0.f);
                    }
                    if (WF) {
                        *(float4*)(fcl + icg * 8)     = a4;
                        *(float4*)(fcl + icg * 8 + 4) = b4;
                    }
                }
                // permute to fragment order: (a.x,b.x,a.y,b.y,a.z,b.z,a.w,b.w)
                uint4* d4 = (uint4*)(dst + icg * (TW * 8));
                d4[0] = make_uint4(f2tf32(a4.x), f2tf32(b4.x),
                                   f2tf32(a4.y), f2tf32(b4.y));
                d4[1] = make_uint4(f2tf32(a4.z), f2tf32(b4.z),
                                   f2tf32(a4.w), f2tf32(b4.w));
            }
        }

        // ---- stage B: plain vector copy of pre-permuted tf32 weights ----
        {
            const uint4* wb = (const uint4*)(wpb + ch * (COUT * PITCH));
            uint4* sb4 = (uint4*)s_b;
#pragma unroll 4
            for (int idx = tid; idx < COUT * PITCH / 4; idx += 256)
                sb4[idx] = wb[idx];
        }
        __syncthreads();

        // ---- MMA over STEPS k-slices ----
#pragma unroll
        for (int s = 0; s < STEPS; s++) {
            const int k   = s / NG;
            const int icg = s - k * NG;
            const int ky  = k / 3, kx = k - (k / 3) * 3;
            const int off = ((ky * NG + icg) * TW + kx) * 8;
            uint2 Af[2 * MT];
#pragma unroll
            for (int i = 0; i < 2 * MT; i++)
                Af[i] = *(const uint2*)(s_a + basew[i] + off);
#pragma unroll
            for (int nc = 0; nc < NC; nc++) {
                uint2 B = *(const uint2*)(s_b + (nc * 8 + g) * PITCH + s * 8 + 2 * t);
#pragma unroll
                for (int mt = 0; mt < MT; mt++)
                    mma_tf32(acc[mt][nc], Af[2*mt].x, Af[2*mt+1].x,
                             Af[2*mt].y, Af[2*mt+1].y, B.x, B.y);
            }
        }
    }

    __syncthreads();   // mainloop smem regions free from here
    float* s_st  = smf + 128;          // [PC][COUT]
    float* s_red = s_st + COUT * PC;   // [8 warps][COUT][2]

    // ---- BN stats straight from accumulators ----
#pragma unroll
    for (int nc = 0; nc < NC; nc++) {
        float s0 = 0.f, s1 = 0.f, q0 = 0.f, q1 = 0.f;
#pragma unroll
        for (int mt = 0; mt < MT; mt++) {
            s0 += acc[mt][nc][0] + acc[mt][nc][2];
            s1 += acc[mt][nc][1] + acc[mt][nc][3];
            q0 += acc[mt][nc][0]*acc[mt][nc][0] + acc[mt][nc][2]*acc[mt][nc][2];
            q1 += acc[mt][nc][1]*acc[mt][nc][1] + acc[mt][nc][3]*acc[mt][nc][3];
        }
#pragma unroll
        for (int off = 4; off < 32; off <<= 1) {
            s0 += __shfl_xor_sync(0xffffffffu, s0, off);
            s1 += __shfl_xor_sync(0xffffffffu, s1, off);
            q0 += __shfl_xor_sync(0xffffffffu, q0, off);
            q1 += __shfl_xor_sync(0xffffffffu, q1, off);
        }
        if (lane < 4) {
            const int cb = nc * 8 + 2 * lane;
            s_red[(wid * COUT + cb)     * 2 + 0] = s0;
            s_red[(wid * COUT + cb)     * 2 + 1] = q0;
            s_red[(wid * COUT + cb + 1) * 2 + 0] = s1;
            s_red[(wid * COUT + cb + 1) * 2 + 1] = q1;
        }
    }

    // ---- frags -> smem staging [PC][COUT] (float2 per frag pair) ----
#pragma unroll
    for (int mt = 0; mt < MT; mt++)
#pragma unroll
        for (int nc = 0; nc < NC; nc++) {
            const int cb = nc * 8 + 2 * t;
            const int p0 = wid * (16 * MT) + mt * 16 + g;
            *(float2*)&s_st[p0 * COUT + cb]       = make_float2(acc[mt][nc][0], acc[mt][nc][1]);
            *(float2*)&s_st[(p0 + 8) * COUT + cb] = make_float2(acc[mt][nc][2], acc[mt][nc][3]);
        }
    __syncthreads();

    // coalesced channel-last store (float4)
    for (int idx = tid; idx < COUT * PC / 4; idx += 256) {
        const int c4  = idx % (COUT / 4);
        const int lp  = idx / (COUT / 4);
        const int img = lp / (R * W);
        const int rem = lp - img * (R * W);
        const int y   = r0 + rem / W;
        const int x   = rem - (rem / W) * W;
        const float4 v = *(const float4*)&s_st[lp * COUT + c4 * 4];
        *(float4*)&out[(((size_t)(img0 + img) * W + y) * W + x) * COUT + c4 * 4] = v;
    }

    if (tid < COUT) {
        float s = 0.f, q = 0.f;
#pragma unroll
        for (int w8 = 0; w8 < 8; w8++) {
            s += s_red[(w8 * COUT + tid) * 2 + 0];
            q += s_red[(w8 * COUT + tid) * 2 + 1];
        }
        atomicAdd(&st_out[tid * 2 + 0], (double)s);
        atomicAdd(&st_out[tid * 2 + 1], (double)q);
    }
}

// ---------------------------------------------------------------------------
// Fused final residual + global average pool (8x8) + FC 64->10 (channel-last)
// ---------------------------------------------------------------------------
__global__ void __launch_bounds__(64)
poolfc_k(const float* __restrict__ h2, const double* __restrict__ st,
         const float* __restrict__ prev, const float* __restrict__ Wfc,
         const float* __restrict__ bfc, float* __restrict__ out)
{
    __shared__ float pooled[64];
    const int n = blockIdx.x, t = threadIdx.x;
    const double cnt = 1024.0 * 64.0;
    double m = st[t*2] / cnt;
    double v = st[t*2+1] / cnt - m * m;
    const float sc = rsqrtf((float)v + 1e-5f);
    const float sh = (float)(-m) * sc;
    const float* hp = h2   + (size_t)n * 64 * 64;
    const float* pp = prev + (size_t)n * 64 * 64;
    float s = 0.f;
#pragma unroll
    for (int i = 0; i < 64; i++)
        s += fmaxf(fmaf(hp[i * 64 + t], sc, sh) + pp[i * 64 + t], 0.f);
    pooled[t] = s * (1.f / 64.f);
    __syncthreads();
    if (t < 10) {
        float a = bfc[t];
#pragma unroll
        for (int c = 0; c < 64; c++) a = fmaf(Wfc[t * 64 + c], pooled[c], a);
        out[n * 10 + t] = a;
    }
}

// ---------------------------------------------------------------------------
// Host-side smem size (mirror of kernel constants)
// ---------------------------------------------------------------------------
static constexpr int cm2(int CINP, int COUT, int HIN, int STRIDE, int ICC,
                         int IMGS, int MT) {
    int W  = HIN / STRIDE;
    int PC = 128 * MT;
    int R  = PC / (W * IMGS);
    int TH = (R - 1) * STRIDE + 3;
    int TW = HIN + 2;
    int K  = ICC * 9;
    int P  = pitchf(K);
    int tile = IMGS * TH * TW * ICC;
    int p1 = tile + COUT * P;
    int p2 = COUT * PC + 16 * COUT;
    int m  = (p1 > p2) ? p1 : p2;
    return (128 + m) * 4;
}

extern "C" void kernel_launch(void* const* d_in, const int* in_sizes, int n_in,
                              void* d_out, int out_size)
{
    (void)in_sizes; (void)n_in; (void)out_size;
    const float* x   = (const float*)d_in[0];
    const float* ow  = (const float*)d_in[1];
    const float* P   = (const float*)d_in[2];
    const float* npar= (const float*)d_in[3];
    const float* Wfc = (const float*)d_in[4];
    const float* bfc = (const float*)d_in[5];
    float* y = (float*)d_out;

    float *A, *B, *C, *D, *w; uint32_t* wp; double* st;
    cudaGetSymbolAddress((void**)&A,  g_bufA);
    cudaGetSymbolAddress((void**)&B,  g_bufB);
    cudaGetSymbolAddress((void**)&C,  g_bufC);
    cudaGetSymbolAddress((void**)&D,  g_bufD);
    cudaGetSymbolAddress((void**)&w,  g_w);
    cudaGetSymbolAddress((void**)&wp, g_wp);
    cudaGetSymbolAddress((void**)&st, g_stats);

    #define SETSM(FN, CINP_, COUT_, HIN_, STRIDE_, ICC_, IMGS_, MT_) \
        cudaFuncSetAttribute(FN, cudaFuncAttributeMaxDynamicSharedMemorySize, \
                             cm2(CINP_, COUT_, HIN_, STRIDE_, ICC_, IMGS_, MT_))

    // 16-ch variants: MINB=6 (75% occ, fits without spills now);
    // 32-out: MINB=4; 64-out: MINB=2
    auto I0  = convt_k< 8, 8,16,32,1, 8,1,2,0, 0,false,6>; SETSM(I0,  8,16,32,1, 8,1,2);
    auto I1  = convt_k<16,16,16,32,1,16,1,2,1, 0,true ,6>; SETSM(I1, 16,16,32,1,16,1,2);
    auto I2  = convt_k<16,16,16,32,1,16,1,2,1, 0,false,6>; SETSM(I2, 16,16,32,1,16,1,2);
    auto I3  = convt_k<16,16,16,32,1,16,1,2,2,16,true ,6>; SETSM(I3, 16,16,32,1,16,1,2);
    auto I4  = convt_k<16,16,32,32,2, 8,1,2,2,16,true ,4>; SETSM(I4, 16,32,32,2, 8,1,2);
    auto I5  = convt_k<32,32,32,16,1, 8,1,2,1, 0,false,4>; SETSM(I5, 32,32,16,1, 8,1,2);
    auto I6  = convt_k<32,32,32,16,1, 8,1,2,3,16,true ,4>; SETSM(I6, 32,32,16,1, 8,1,2);
    auto I7  = convt_k<32,32,32,16,1, 8,1,2,2,32,true ,4>; SETSM(I7, 32,32,16,1, 8,1,2);
    auto I8  = convt_k<32,32,64,16,2, 8,4,2,2,32,true ,2>; SETSM(I8, 32,64,16,2, 8,4,2);
    auto I9  = convt_k<64,64,64, 8,1,16,4,2,1, 0,false,2>; SETSM(I9, 64,64, 8,1,16,4,2);
    auto I10 = convt_k<64,64,64, 8,1,16,4,2,3,32,true ,2>; SETSM(I10,64,64, 8,1,16,4,2);
    auto I11 = convt_k<64,64,64, 8,1,16,4,2,2,64,true ,2>; SETSM(I11,64,64, 8,1,16,4,2);
    #undef SETSM

    auto ST = [&](int l) { return st + l * 128; };
    auto WL = [&](int l) { return wp + PO_H[l]; };

    zstats_k<<<(19*64*2 + 255)/256, 256>>>(st);
    wbuild_k<<<(D_TOT + 255)/256, 256>>>(ow, P, npar, w);
    wperm_k<<<(WP_TOT + 255)/256, 256>>>(w, wp);
    xpose_k<<<4096, 256>>>(x, D);   // NCHW 3ch -> NHWC-8 (zero padded)

    const int S1 = cm2( 8,16,32,1, 8,1,2);
    const int S2 = cm2(16,16,32,1,16,1,2);
    const int S3 = cm2(16,32,32,2, 8,1,2);
    const int S4 = cm2(32,32,16,1, 8,1,2);
    const int S5 = cm2(32,64,16,2, 8,4,2);
    const int S6 = cm2(64,64, 8,1,16,4,2);

    // layer 0 (channel-last padded input in D)
    I0 <<<4096,256,S1>>>(D, WL(0), A, nullptr, ST(0), nullptr, nullptr);
    // block 1
    I1 <<<4096,256,S2>>>(A, WL(1), B, ST(0),  ST(1), nullptr, C);
    I2 <<<4096,256,S2>>>(B, WL(2), A, ST(1),  ST(2), nullptr, nullptr);
    // block 2
    I3 <<<4096,256,S2>>>(A, WL(3), B, ST(2),  ST(3), C, D);
    I2 <<<4096,256,S2>>>(B, WL(4), C, ST(3),  ST(4), nullptr, nullptr);
    // block 3
    I3 <<<4096,256,S2>>>(C, WL(5), B, ST(4),  ST(5), D, A);
    I2 <<<4096,256,S2>>>(B, WL(6), D, ST(5),  ST(6), nullptr, nullptr);
    // block 4 (16->32, stride 2)
    I4 <<<1024,256,S3>>>(D, WL(7), B, ST(6),  ST(7), A, C);
    I5 <<<1024,256,S4>>>(B, WL(8), A, ST(7),  ST(8), nullptr, nullptr);
    // block 5 (MODE3 pad shortcut, prev 16ch@32)
    I6 <<<1024,256,S4>>>(A, WL(9), B, ST(8),  ST(9), C, D);
    I5 <<<1024,256,S4>>>(B, WL(10),C, ST(9),  ST(10),nullptr, nullptr);
    // block 6
    I7 <<<1024,256,S4>>>(C, WL(11),B, ST(10), ST(11),D, A);
    I5 <<<1024,256,S4>>>(B, WL(12),D, ST(11), ST(12),nullptr, nullptr);
    // block 7 (32->64, stride 2)
    I8 <<< 256,256,S5>>>(D, WL(13),B, ST(12), ST(13),A, C);
    I9 <<< 256,256,S6>>>(B, WL(14),A, ST(13), ST(14),nullptr, nullptr);
    // block 8 (MODE3 pad shortcut, prev 32ch@16)
    I10<<< 256,256,S6>>>(A, WL(15),B, ST(14), ST(15),C, D);
    I9 <<< 256,256,S6>>>(B, WL(16),C, ST(15), ST(16),nullptr, nullptr);
    // block 9
    I11<<< 256,256,S6>>>(C, WL(17),B, ST(16), ST(17),D, A);
    I9 <<< 256,256,S6>>>(B, WL(18),D, ST(17), ST(18),nullptr, nullptr);
    // fused final residual + pool + fc
    poolfc_k<<<NB,64>>>(D, ST(18), A, Wfc, bfc, y);
}

// round 15
// speedup vs baseline: 1.0465x; 1.0280x over previous
#include <cuda_runtime.h>
#include <cuda_bf16.h>
#include <cstdint>
#include <cstdio>

// ---------------------------------------------------------------------------
// Problem constants
// ---------------------------------------------------------------------------
#define NB 1024
static const int D_TOT = 267696;

// permuted tf32 weight buffer offsets (see wperm_k); ICC per layer:
// {8,16,16,16,16,16,16,8,8,8,8,8,8,8,16,16,16,16,16}
static const int PO_H[19] = {0,1152,3584,6016,8448,10880,13312,15744,20352,29568,
                             38784,48000,57216,66432,84864,123776,162688,201600,240512};
#define WP_TOT 279424

__constant__ int c_PO[19]   = {0,1152,3584,6016,8448,10880,13312,15744,20352,29568,
                               38784,48000,57216,66432,84864,123776,162688,201600,240512};
__constant__ int c_WOFF[19] = {0,432,2736,5040,7344,9648,11952,14256,18864,28080,
                               37296,46512,55728,64944,83376,120240,157104,193968,230832};
__constant__ int c_LCIN[19]  = {3,16,16,16,16,16,16,16,32,32,32,32,32,32,64,64,64,64,64};
__constant__ int c_LICC[19]  = {8,16,16,16,16,16,16,8,8,8,8,8,8,8,16,16,16,16,16};
__constant__ int c_LCOUT[19] = {16,16,16,16,16,16,16,32,32,32,32,32,32,64,64,64,64,64,64};
__constant__ int c_LPITCH[19]= {72,152,152,152,152,152,152,72,72,72,72,72,72,72,152,152,152,152,152};

// ---------------------------------------------------------------------------
// Device scratch
// ---------------------------------------------------------------------------
#define BUF_ELEMS (1024*16*32*32)
__device__ float    g_bufA[BUF_ELEMS];
__device__ float    g_bufB[BUF_ELEMS];
__device__ float    g_bufC[BUF_ELEMS];
__device__ float    g_bufD[BUF_ELEMS];
__device__ float    g_w[267696];       // natural per-layer layout: [oc][ic][3][3]
__device__ uint32_t g_wp[WP_TOT];      // permuted tf32 smem-image weights
__device__ double   g_stats[19*64*2];  // per layer, per channel: sum, sumsq

// ---------------------------------------------------------------------------
// helpers
// ---------------------------------------------------------------------------
__host__ __device__ constexpr int pitchf(int K) {
    int p = K;
    while (!((p % 32) == 8 || (p % 32) == 24)) p++;
    return p;
}
__device__ __forceinline__ uint32_t f2tf32(float v) {
    uint32_t u; asm("cvt.rna.tf32.f32 %0, %1;" : "=r"(u) : "f"(v)); return u;
}
__device__ __forceinline__ void mma_tf32(float c[4],
                                         uint32_t a0, uint32_t a1, uint32_t a2, uint32_t a3,
                                         uint32_t b0, uint32_t b1) {
    asm volatile(
        "mma.sync.aligned.m16n8k8.row.col.f32.tf32.tf32.f32 "
        "{%0,%1,%2,%3}, {%4,%5,%6,%7}, {%8,%9}, {%0,%1,%2,%3};"
        : "+f"(c[0]), "+f"(c[1]), "+f"(c[2]), "+f"(c[3])
        : "r"(a0), "r"(a1), "r"(a2), "r"(a3), "r"(b0), "r"(b1));
}

// ---------------------------------------------------------------------------
__global__ void zstats_k(double* __restrict__ st) {
    int i = blockIdx.x * blockDim.x + threadIdx.x;
    if (i < 19*64*2) st[i] = 0.0;
}

__global__ void wbuild_k(const float* __restrict__ ow, const float* __restrict__ P,
                         const float* __restrict__ npar, float* __restrict__ wt) {
    __shared__ float s_np[40];
    if (threadIdx.x < 40) s_np[threadIdx.x] = npar[threadIdx.x];
    __syncthreads();
    int d = blockIdx.x * blockDim.x + threadIdx.x;
    if (d >= D_TOT) return;
    float a = ow[d];
#pragma unroll
    for (int j = 0; j < 40; j++)
        a = fmaf(s_np[j], P[(size_t)j * D_TOT + d], a);
    wt[d] = a;
}

// Permute weights into the exact smem image the conv consumes (rna-converted).
__global__ void wperm_k(const float* __restrict__ w, uint32_t* __restrict__ wp) {
    int i = blockIdx.x * blockDim.x + threadIdx.x;
    if (i >= WP_TOT) return;
    int l = 18;
    while (l > 0 && i < c_PO[l]) l--;
    const int r     = i - c_PO[l];
    const int CINR  = c_LCIN[l];
    const int ICC   = c_LICC[l];
    const int COUT  = c_LCOUT[l];
    const int PITCH = c_LPITCH[l];
    const int K     = ICC * 9;
    const int NG    = ICC / 8;
    const int cs    = COUT * PITCH;
    const int ch    = r / cs;
    const int r2    = r - ch * cs;
    const int oc    = r2 / PITCH;
    const int pos   = r2 - oc * PITCH;
    float v = 0.f;
    if (pos < K) {
        const int s    = pos >> 3, phys = pos & 7;
        const int u    = (phys & 1) ? (phys >> 1) + 4 : (phys >> 1);
        const int k    = s / NG, icg = s - (s / NG) * NG;
        const int ic   = ch * ICC + icg * 8 + u;
        if (ic < CINR) v = w[c_WOFF[l] + (oc * CINR + ic) * 9 + k];
    }
    wp[i] = f2tf32(v);
}

// Transpose NCHW 3-channel input to NHWC-8 (channels 3..7 zero).
__global__ void __launch_bounds__(256)
xpose_k(const float* __restrict__ in, float* __restrict__ out) {
    const int idx = blockIdx.x * 256 + threadIdx.x;   // (n*1024 + y*32 + x)
    const int n  = idx >> 10;
    const int hw = idx & 1023;
    const float* ib = in + (size_t)n * 3 * 1024 + hw;
    float4 a = make_float4(__ldg(ib), __ldg(ib + 1024), __ldg(ib + 2048), 0.f);
    float4 b = make_float4(0.f, 0.f, 0.f, 0.f);
    float4* ob = (float4*)(out + (size_t)idx * 8);
    ob[0] = a;
    ob[1] = b;
}

// ---------------------------------------------------------------------------
// Direct-from-tile tensor-core conv, channel-last activations.
//  Two-phase staging (batch loads, then transform+store). Activations are
//  stored to smem as RAW fp32 bits: the tf32 MMA reads bits[31:13] only
//  (CUTLASS fast-tf32/truncate path) -> no cvt in the hot staging loop.
//  MT = m16-tiles per warp; positions per CTA = 128*MT. MINB = min blocks/SM.
//  MODE 0: plain; 1: relu(bn(in)); 2: +identity prev; 3: +padded/strided prev.
//  WF: also write transformed activation to `fused` (channel-last).
// ---------------------------------------------------------------------------
template<int CINR, int CINP, int COUT, int HIN, int STRIDE, int ICC, int IMGS,
         int MT, int MODE, int CPREV, bool WF, int MINB>
__global__ void __launch_bounds__(256, MINB)
convt_k(const float* __restrict__ in, const uint32_t* __restrict__ wpb,
        float* __restrict__ out, const double* __restrict__ st_in,
        double* __restrict__ st_out, const float* __restrict__ prev,
        float* __restrict__ fused)
{
    constexpr int W     = HIN / STRIDE;
    constexpr int NPOS  = W * W;
    constexpr int PC    = 128 * MT;              // positions per CTA
    constexpr int R     = PC / (W * IMGS);
    constexpr int SPI   = (IMGS == 1) ? (NPOS / PC) : 1;
    constexpr int TH    = (R - 1) * STRIDE + 3;
    constexpr int TW    = HIN + 2;
    constexpr int NG    = ICC / 8;
    constexpr int NCH   = CINP / ICC;
    constexpr int K     = ICC * 9;
    constexpr int PITCH = pitchf(K);
    constexpr int STEPS = K / 8;
    constexpr int NC    = COUT / 8;
    constexpr int TILEW = IMGS * TH * TW * ICC;
    constexpr int PADF  = (MODE == 3) ? (CINR - CPREV) / 2 : 0;

    extern __shared__ float smf[];
    float*    s_sc = smf;
    float*    s_sh = smf + 64;
    uint32_t* s_a  = (uint32_t*)(smf + 128);
    uint32_t* s_b  = s_a + TILEW;

    const int tid = threadIdx.x, wid = tid >> 5, lane = tid & 31;
    const int g = lane >> 2, t = lane & 3;

    const int img0 = (IMGS == 1) ? (blockIdx.x / SPI) : blockIdx.x * IMGS;
    const int r0   = (IMGS == 1) ? (blockIdx.x % SPI) * R : 0;

    if (MODE >= 1 && tid < CINR) {
        const double cnt = 1024.0 * HIN * HIN;
        double mm = st_in[tid*2]   / cnt;
        double vv = st_in[tid*2+1] / cnt - mm * mm;
        float rs = rsqrtf((float)vv + 1e-5f);
        s_sc[tid] = rs;
        s_sh[tid] = (float)(-mm) * rs;
    }
    if (MODE >= 1) __syncthreads();

    // row-base word offsets into the tile (rows g, g+8, ... per m16 tile)
    int basew[2 * MT];
#pragma unroll
    for (int i = 0; i < 2 * MT; i++) {
        const int p   = wid * (16 * MT) + i * 8 + g;
        const int img = p / (R * W);
        const int rem = p - img * (R * W);
        const int y   = rem / W, x = rem - (rem / W) * W;
        basew[i] = (((img * TH + y * STRIDE) * NG) * TW + x * STRIDE) * 8 + 2 * t;
    }

    float acc[MT][NC][4];
#pragma unroll
    for (int mt = 0; mt < MT; mt++)
#pragma unroll
        for (int nc = 0; nc < NC; nc++)
#pragma unroll
            for (int i = 0; i < 4; i++) acc[mt][nc][i] = 0.f;

    for (int ch = 0; ch < NCH; ch++) {
        const int ic0 = ch * ICC;
        __syncthreads();

        // ---- stage input tile: phase-1 batch loads, phase-2 transform+store ----
        for (int idx = tid; idx < IMGS * TH * TW; idx += 256) {
            const int img = idx / (TH * TW);
            const int rr  = idx - img * (TH * TW);
            const int ty  = rr / TW, tx = rr - (rr / TW) * TW;
            const int yi  = r0 * STRIDE - 1 + ty;
            const int xi  = tx - 1;
            const bool ok = (unsigned)yi < (unsigned)HIN && (unsigned)xi < (unsigned)HIN;
            const int  n  = img0 + img;
            uint32_t* dst = s_a + ((img * TH + ty) * NG) * (TW * 8) + tx * 8;

            const float* gcl = in + (((size_t)n * HIN + yi) * HIN + xi) * CINR + ic0;
            const float* pcl = nullptr;
            if (MODE == 2)
                pcl = prev + (((size_t)n * HIN + yi) * HIN + xi) * CPREV + ic0;
            if (MODE == 3)
                pcl = prev + (((size_t)n * (2*HIN) + 2*yi) * (2*HIN) + 2*xi) * CPREV
                           + (ic0 - PADF);
            float* fcl = nullptr;
            if (WF) fcl = fused + (((size_t)n * HIN + yi) * HIN + xi) * CINR + ic0;

            // phase 1: issue all loads (input + shortcut) concurrently
            float4 ia[NG][2], pa[NG][2];
#pragma unroll
            for (int icg = 0; icg < NG; icg++) {
                if (ok) {
                    ia[icg][0] = *(const float4*)(gcl + icg * 8);
                    ia[icg][1] = *(const float4*)(gcl + icg * 8 + 4);
                } else {
                    ia[icg][0] = make_float4(0.f,0.f,0.f,0.f);
                    ia[icg][1] = make_float4(0.f,0.f,0.f,0.f);
                }
            }
            if (MODE == 2 || MODE == 3) {
#pragma unroll
                for (int icg = 0; icg < NG; icg++) {
                    bool pv = ok;
                    if (MODE == 3) {
                        const int gic0 = ic0 + icg * 8 - PADF;
                        pv = ok && (gic0 >= 0) && (gic0 + 8 <= CPREV);
                    }
                    if (pv) {
                        pa[icg][0] = *(const float4*)(pcl + icg * 8);
                        pa[icg][1] = *(const float4*)(pcl + icg * 8 + 4);
                    } else {
                        pa[icg][0] = make_float4(0.f,0.f,0.f,0.f);
                        pa[icg][1] = make_float4(0.f,0.f,0.f,0.f);
                    }
                }
            }

            // phase 2: transform + store (raw fp32 bits; MMA truncates to tf32)
#pragma unroll
            for (int icg = 0; icg < NG; icg++) {
                float4 a4 = ia[icg][0], b4 = ia[icg][1];
                if (MODE >= 1 && ok) {
                    const float4 sa = *(const float4*)&s_sc[ic0 + icg*8];
                    const float4 sb = *(const float4*)&s_sc[ic0 + icg*8 + 4];
                    const float4 ha = *(const float4*)&s_sh[ic0 + icg*8];
                    const float4 hb = *(const float4*)&s_sh[ic0 + icg*8 + 4];
                    a4.x = fmaf(a4.x, sa.x, ha.x); a4.y = fmaf(a4.y, sa.y, ha.y);
                    a4.z = fmaf(a4.z, sa.z, ha.z); a4.w = fmaf(a4.w, sa.w, ha.w);
                    b4.x = fmaf(b4.x, sb.x, hb.x); b4.y = fmaf(b4.y, sb.y, hb.y);
                    b4.z = fmaf(b4.z, sb.z, hb.z); b4.w = fmaf(b4.w, sb.w, hb.w);
                    if (MODE >= 2) {
                        a4.x += pa[icg][0].x; a4.y += pa[icg][0].y;
                        a4.z += pa[icg][0].z; a4.w += pa[icg][0].w;
                        b4.x += pa[icg][1].x; b4.y += pa[icg][1].y;
                        b4.z += pa[icg][1].z; b4.w += pa[icg][1].w;
                    }
                    a4.x = fmaxf(a4.x, 0.f); a4.y = fmaxf(a4.y, 0.f);
                    a4.z = fmaxf(a4.z, 0.f); a4.w = fmaxf(a4.w, 0.f);
                    b4.x = fmaxf(b4.x, 0.f); b4.y = fmaxf(b4.y, 0.f);
                    b4.z = fmaxf(b4.z, 0.f); b4.w = fmaxf(b4.w, 0.f);
                }
                if (WF && ok) {
                    *(float4*)(fcl + icg * 8)     = a4;
                    *(float4*)(fcl + icg * 8 + 4) = b4;
                }
                // permute to fragment order: (a.x,b.x,a.y,b.y,a.z,b.z,a.w,b.w)
                uint4* d4 = (uint4*)(dst + icg * (TW * 8));
                d4[0] = make_uint4(__float_as_uint(a4.x), __float_as_uint(b4.x),
                                   __float_as_uint(a4.y), __float_as_uint(b4.y));
                d4[1] = make_uint4(__float_as_uint(a4.z), __float_as_uint(b4.z),
                                   __float_as_uint(a4.w), __float_as_uint(b4.w));
            }
        }

        // ---- stage B: plain vector copy of pre-permuted tf32 weights ----
        {
            const uint4* wb = (const uint4*)(wpb + ch * (COUT * PITCH));
            uint4* sb4 = (uint4*)s_b;
#pragma unroll 4
            for (int idx = tid; idx < COUT * PITCH / 4; idx += 256)
                sb4[idx] = wb[idx];
        }
        __syncthreads();

        // ---- MMA over STEPS k-slices ----
#pragma unroll
        for (int s = 0; s < STEPS; s++) {
            const int k   = s / NG;
            const int icg = s - k * NG;
            const int ky  = k / 3, kx = k - (k / 3) * 3;
            const int off = ((ky * NG + icg) * TW + kx) * 8;
            uint2 Af[2 * MT];
#pragma unroll
            for (int i = 0; i < 2 * MT; i++)
                Af[i] = *(const uint2*)(s_a + basew[i] + off);
#pragma unroll
            for (int nc = 0; nc < NC; nc++) {
                uint2 B = *(const uint2*)(s_b + (nc * 8 + g) * PITCH + s * 8 + 2 * t);
#pragma unroll
                for (int mt = 0; mt < MT; mt++)
                    mma_tf32(acc[mt][nc], Af[2*mt].x, Af[2*mt+1].x,
                             Af[2*mt].y, Af[2*mt+1].y, B.x, B.y);
            }
        }
    }

    __syncthreads();   // mainloop smem regions free from here
    float* s_st  = smf + 128;          // [PC][COUT]
    float* s_red = s_st + COUT * PC;   // [8 warps][COUT][2]

    // ---- BN stats straight from accumulators ----
#pragma unroll
    for (int nc = 0; nc < NC; nc++) {
        float s0 = 0.f, s1 = 0.f, q0 = 0.f, q1 = 0.f;
#pragma unroll
        for (int mt = 0; mt < MT; mt++) {
            s0 += acc[mt][nc][0] + acc[mt][nc][2];
            s1 += acc[mt][nc][1] + acc[mt][nc][3];
            q0 += acc[mt][nc][0]*acc[mt][nc][0] + acc[mt][nc][2]*acc[mt][nc][2];
            q1 += acc[mt][nc][1]*acc[mt][nc][1] + acc[mt][nc][3]*acc[mt][nc][3];
        }
#pragma unroll
        for (int off = 4; off < 32; off <<= 1) {
            s0 += __shfl_xor_sync(0xffffffffu, s0, off);
            s1 += __shfl_xor_sync(0xffffffffu, s1, off);
            q0 += __shfl_xor_sync(0xffffffffu, q0, off);
            q1 += __shfl_xor_sync(0xffffffffu, q1, off);
        }
        if (lane < 4) {
            const int cb = nc * 8 + 2 * lane;
            s_red[(wid * COUT + cb)     * 2 + 0] = s0;
            s_red[(wid * COUT + cb)     * 2 + 1] = q0;
            s_red[(wid * COUT + cb + 1) * 2 + 0] = s1;
            s_red[(wid * COUT + cb + 1) * 2 + 1] = q1;
        }
    }

    // ---- frags -> smem staging [PC][COUT] (float2 per frag pair) ----
#pragma unroll
    for (int mt = 0; mt < MT; mt++)
#pragma unroll
        for (int nc = 0; nc < NC; nc++) {
            const int cb = nc * 8 + 2 * t;
            const int p0 = wid * (16 * MT) + mt * 16 + g;
            *(float2*)&s_st[p0 * COUT + cb]       = make_float2(acc[mt][nc][0], acc[mt][nc][1]);
            *(float2*)&s_st[(p0 + 8) * COUT + cb] = make_float2(acc[mt][nc][2], acc[mt][nc][3]);
        }
    __syncthreads();

    // coalesced channel-last store (float4)
    for (int idx = tid; idx < COUT * PC / 4; idx += 256) {
        const int c4  = idx % (COUT / 4);
        const int lp  = idx / (COUT / 4);
        const int img = lp / (R * W);
        const int rem = lp - img * (R * W);
        const int y   = r0 + rem / W;
        const int x   = rem - (rem / W) * W;
        const float4 v = *(const float4*)&s_st[lp * COUT + c4 * 4];
        *(float4*)&out[(((size_t)(img0 + img) * W + y) * W + x) * COUT + c4 * 4] = v;
    }

    if (tid < COUT) {
        float s = 0.f, q = 0.f;
#pragma unroll
        for (int w8 = 0; w8 < 8; w8++) {
            s += s_red[(w8 * COUT + tid) * 2 + 0];
            q += s_red[(w8 * COUT + tid) * 2 + 1];
        }
        atomicAdd(&st_out[tid * 2 + 0], (double)s);
        atomicAdd(&st_out[tid * 2 + 1], (double)q);
    }
}

// ---------------------------------------------------------------------------
// Fused final residual + global average pool (8x8) + FC 64->10 (channel-last)
// ---------------------------------------------------------------------------
__global__ void __launch_bounds__(64)
poolfc_k(const float* __restrict__ h2, const double* __restrict__ st,
         const float* __restrict__ prev, const float* __restrict__ Wfc,
         const float* __restrict__ bfc, float* __restrict__ out)
{
    __shared__ float pooled[64];
    const int n = blockIdx.x, t = threadIdx.x;
    const double cnt = 1024.0 * 64.0;
    double m = st[t*2] / cnt;
    double v = st[t*2+1] / cnt - m * m;
    const float sc = rsqrtf((float)v + 1e-5f);
    const float sh = (float)(-m) * sc;
    const float* hp = h2   + (size_t)n * 64 * 64;
    const float* pp = prev + (size_t)n * 64 * 64;
    float s = 0.f;
#pragma unroll
    for (int i = 0; i < 64; i++)
        s += fmaxf(fmaf(hp[i * 64 + t], sc, sh) + pp[i * 64 + t], 0.f);
    pooled[t] = s * (1.f / 64.f);
    __syncthreads();
    if (t < 10) {
        float a = bfc[t];
#pragma unroll
        for (int c = 0; c < 64; c++) a = fmaf(Wfc[t * 64 + c], pooled[c], a);
        out[n * 10 + t] = a;
    }
}

// ---------------------------------------------------------------------------
// Host-side smem size (mirror of kernel constants)
// ---------------------------------------------------------------------------
static constexpr int cm2(int CINP, int COUT, int HIN, int STRIDE, int ICC,
                         int IMGS, int MT) {
    int W  = HIN / STRIDE;
    int PC = 128 * MT;
    int R  = PC / (W * IMGS);
    int TH = (R - 1) * STRIDE + 3;
    int TW = HIN + 2;
    int K  = ICC * 9;
    int P  = pitchf(K);
    int tile = IMGS * TH * TW * ICC;
    int p1 = tile + COUT * P;
    int p2 = COUT * PC + 16 * COUT;
    int m  = (p1 > p2) ? p1 : p2;
    return (128 + m) * 4;
}

extern "C" void kernel_launch(void* const* d_in, const int* in_sizes, int n_in,
                              void* d_out, int out_size)
{
    (void)in_sizes; (void)n_in; (void)out_size;
    const float* x   = (const float*)d_in[0];
    const float* ow  = (const float*)d_in[1];
    const float* P   = (const float*)d_in[2];
    const float* npar= (const float*)d_in[3];
    const float* Wfc = (const float*)d_in[4];
    const float* bfc = (const float*)d_in[5];
    float* y = (float*)d_out;

    float *A, *B, *C, *D, *w; uint32_t* wp; double* st;
    cudaGetSymbolAddress((void**)&A,  g_bufA);
    cudaGetSymbolAddress((void**)&B,  g_bufB);
    cudaGetSymbolAddress((void**)&C,  g_bufC);
    cudaGetSymbolAddress((void**)&D,  g_bufD);
    cudaGetSymbolAddress((void**)&w,  g_w);
    cudaGetSymbolAddress((void**)&wp, g_wp);
    cudaGetSymbolAddress((void**)&st, g_stats);

    #define SETSM(FN, CINP_, COUT_, HIN_, STRIDE_, ICC_, IMGS_, MT_) \
        cudaFuncSetAttribute(FN, cudaFuncAttributeMaxDynamicSharedMemorySize, \
                             cm2(CINP_, COUT_, HIN_, STRIDE_, ICC_, IMGS_, MT_))

    // EXACT R11 (1241us) launch-bounds config
    auto I0  = convt_k< 8, 8,16,32,1, 8,1,2,0, 0,false,5>; SETSM(I0,  8,16,32,1, 8,1,2);
    auto I1  = convt_k<16,16,16,32,1,16,1,2,1, 0,true ,5>; SETSM(I1, 16,16,32,1,16,1,2);
    auto I2  = convt_k<16,16,16,32,1,16,1,2,1, 0,false,5>; SETSM(I2, 16,16,32,1,16,1,2);
    auto I3  = convt_k<16,16,16,32,1,16,1,2,2,16,true ,4>; SETSM(I3, 16,16,32,1,16,1,2);
    auto I4  = convt_k<16,16,32,32,2, 8,1,2,2,16,true ,4>; SETSM(I4, 16,32,32,2, 8,1,2);
    auto I5  = convt_k<32,32,32,16,1, 8,1,2,1, 0,false,4>; SETSM(I5, 32,32,16,1, 8,1,2);
    auto I6  = convt_k<32,32,32,16,1, 8,1,2,3,16,true ,4>; SETSM(I6, 32,32,16,1, 8,1,2);
    auto I7  = convt_k<32,32,32,16,1, 8,1,2,2,32,true ,4>; SETSM(I7, 32,32,16,1, 8,1,2);
    auto I8  = convt_k<32,32,64,16,2, 8,4,2,2,32,true ,2>; SETSM(I8, 32,64,16,2, 8,4,2);
    auto I9  = convt_k<64,64,64, 8,1,16,4,2,1, 0,false,2>; SETSM(I9, 64,64, 8,1,16,4,2);
    auto I10 = convt_k<64,64,64, 8,1,16,4,2,3,32,true ,2>; SETSM(I10,64,64, 8,1,16,4,2);
    auto I11 = convt_k<64,64,64, 8,1,16,4,2,2,64,true ,2>; SETSM(I11,64,64, 8,1,16,4,2);
    #undef SETSM

    auto ST = [&](int l) { return st + l * 128; };
    auto WL = [&](int l) { return wp + PO_H[l]; };

    zstats_k<<<(19*64*2 + 255)/256, 256>>>(st);
    wbuild_k<<<(D_TOT + 255)/256, 256>>>(ow, P, npar, w);
    wperm_k<<<(WP_TOT + 255)/256, 256>>>(w, wp);
    xpose_k<<<4096, 256>>>(x, D);   // NCHW 3ch -> NHWC-8 (zero padded)

    const int S1 = cm2( 8,16,32,1, 8,1,2);
    const int S2 = cm2(16,16,32,1,16,1,2);
    const int S3 = cm2(16,32,32,2, 8,1,2);
    const int S4 = cm2(32,32,16,1, 8,1,2);
    const int S5 = cm2(32,64,16,2, 8,4,2);
    const int S6 = cm2(64,64, 8,1,16,4,2);

    // layer 0 (channel-last padded input in D)
    I0 <<<4096,256,S1>>>(D, WL(0), A, nullptr, ST(0), nullptr, nullptr);
    // block 1
    I1 <<<4096,256,S2>>>(A, WL(1), B, ST(0),  ST(1), nullptr, C);
    I2 <<<4096,256,S2>>>(B, WL(2), A, ST(1),  ST(2), nullptr, nullptr);
    // block 2
    I3 <<<4096,256,S2>>>(A, WL(3), B, ST(2),  ST(3), C, D);
    I2 <<<4096,256,S2>>>(B, WL(4), C, ST(3),  ST(4), nullptr, nullptr);
    // block 3
    I3 <<<4096,256,S2>>>(C, WL(5), B, ST(4),  ST(5), D, A);
    I2 <<<4096,256,S2>>>(B, WL(6), D, ST(5),  ST(6), nullptr, nullptr);
    // block 4 (16->32, stride 2)
    I4 <<<1024,256,S3>>>(D, WL(7), B, ST(6),  ST(7), A, C);
    I5 <<<1024,256,S4>>>(B, WL(8), A, ST(7),  ST(8), nullptr, nullptr);
    // block 5 (MODE3 pad shortcut, prev 16ch@32)
    I6 <<<1024,256,S4>>>(A, WL(9), B, ST(8),  ST(9), C, D);
    I5 <<<1024,256,S4>>>(B, WL(10),C, ST(9),  ST(10),nullptr, nullptr);
    // block 6
    I7 <<<1024,256,S4>>>(C, WL(11),B, ST(10), ST(11),D, A);
    I5 <<<1024,256,S4>>>(B, WL(12),D, ST(11), ST(12),nullptr, nullptr);
    // block 7 (32->64, stride 2)
    I8 <<< 256,256,S5>>>(D, WL(13),B, ST(12), ST(13),A, C);
    I9 <<< 256,256,S6>>>(B, WL(14),A, ST(13), ST(14),nullptr, nullptr);
    // block 8 (MODE3 pad shortcut, prev 32ch@16)
    I10<<< 256,256,S6>>>(A, WL(15),B, ST(14), ST(15),C, D);
    I9 <<< 256,256,S6>>>(B, WL(16),C, ST(15), ST(16),nullptr, nullptr);
    // block 9
    I11<<< 256,256,S6>>>(C, WL(17),B, ST(16), ST(17),D, A);
    I9 <<< 256,256,S6>>>(B, WL(18),D, ST(17), ST(18),nullptr, nullptr);
    // fused final residual + pool + fc
    poolfc_k<<<NB,64>>>(D, ST(18), A, Wfc, bfc, y);
}

// round 16
// speedup vs baseline: 1.2392x; 1.1841x over previous
#include <cuda_runtime.h>
#include <cuda_fp16.h>
#include <cstdint>
#include <cstdio>

// ---------------------------------------------------------------------------
// Problem constants
// ---------------------------------------------------------------------------
#define NB 1024
static const int D_TOT = 267696;

// fp16-packed permuted weight buffer, word offsets per layer.
// All layers use ICC=16 (K=144, 9 k16-steps), PITCH = 72 words (144 halfs).
static const int PO_H[19] = {0,1152,2304,3456,4608,5760,6912,8064,10368,14976,
                             19584,24192,28800,33408,42624,61056,79488,97920,116352};
#define WP_TOT 134784

__constant__ int c_PO[19]   = {0,1152,2304,3456,4608,5760,6912,8064,10368,14976,
                               19584,24192,28800,33408,42624,61056,79488,97920,116352};
__constant__ int c_WOFF[19] = {0,432,2736,5040,7344,9648,11952,14256,18864,28080,
                               37296,46512,55728,64944,83376,120240,157104,193968,230832};
__constant__ int c_LCIN[19]  = {3,16,16,16,16,16,16,16,32,32,32,32,32,32,64,64,64,64,64};
__constant__ int c_LCINB[19] = {16,16,16,16,16,16,16,16,32,32,32,32,32,32,64,64,64,64,64};
__constant__ int c_LCOUT[19] = {16,16,16,16,16,16,16,32,32,32,32,32,32,64,64,64,64,64,64};

// ---------------------------------------------------------------------------
// Device scratch
// ---------------------------------------------------------------------------
#define BUF_ELEMS (1024*16*32*32)
__device__ float    g_bufA[BUF_ELEMS];
__device__ float    g_bufB[BUF_ELEMS];
__device__ float    g_bufC[BUF_ELEMS];
__device__ float    g_bufD[BUF_ELEMS];
__device__ float    g_w[267696];       // natural per-layer layout: [oc][ic][3][3]
__device__ uint32_t g_wp[WP_TOT];      // fp16-packed permuted weights
__device__ double   g_stats[19*64*2];  // per layer, per channel: sum, sumsq

// ---------------------------------------------------------------------------
// helpers
// ---------------------------------------------------------------------------
__device__ __forceinline__ uint32_t packh(float a, float b) {
    __half2 h = __floats2half2_rn(a, b);
    return *reinterpret_cast<uint32_t*>(&h);
}
__device__ __forceinline__ void mma_f16(float c[4],
                                        uint32_t a0, uint32_t a1, uint32_t a2, uint32_t a3,
                                        uint32_t b0, uint32_t b1) {
    asm volatile(
        "mma.sync.aligned.m16n8k16.row.col.f32.f16.f16.f32 "
        "{%0,%1,%2,%3}, {%4,%5,%6,%7}, {%8,%9}, {%0,%1,%2,%3};"
        : "+f"(c[0]), "+f"(c[1]), "+f"(c[2]), "+f"(c[3])
        : "r"(a0), "r"(a1), "r"(a2), "r"(a3), "r"(b0), "r"(b1));
}

// ---------------------------------------------------------------------------
__global__ void zstats_k(double* __restrict__ st) {
    int i = blockIdx.x * blockDim.x + threadIdx.x;
    if (i < 19*64*2) st[i] = 0.0;
}

__global__ void wbuild_k(const float* __restrict__ ow, const float* __restrict__ P,
                         const float* __restrict__ npar, float* __restrict__ wt) {
    __shared__ float s_np[40];
    if (threadIdx.x < 40) s_np[threadIdx.x] = npar[threadIdx.x];
    __syncthreads();
    int d = blockIdx.x * blockDim.x + threadIdx.x;
    if (d >= D_TOT) return;
    float a = ow[d];
#pragma unroll
    for (int j = 0; j < 40; j++)
        a = fmaf(s_np[j], P[(size_t)j * D_TOT + d], a);
    wt[d] = a;
}

// Permute + fp16-pack weights into the exact smem image the conv consumes.
// Per layer, per chunk ch: [oc][72 words]; word w: s16 = w/8 (k16 group =
// kpos 0..8), j = w%8, pair p = (j&1) ? j/2+4 : j/2, channels c = 2p, 2p+1.
__global__ void wperm_k(const float* __restrict__ w, uint32_t* __restrict__ wp) {
    int i = blockIdx.x * blockDim.x + threadIdx.x;
    if (i >= WP_TOT) return;
    int l = 18;
    while (l > 0 && i < c_PO[l]) l--;
    const int r     = i - c_PO[l];
    const int CINR  = c_LCIN[l];
    const int COUT  = c_LCOUT[l];
    const int cs    = COUT * 72;
    const int ch    = r / cs;
    const int r2    = r - ch * cs;
    const int oc    = r2 / 72;
    const int wd    = r2 - oc * 72;
    const int s16   = wd >> 3;            // kpos 0..8
    const int j     = wd & 7;
    const int p     = (j & 1) ? (j >> 1) + 4 : (j >> 1);
    const int ic0   = ch * 16 + 2 * p;
    float v0 = 0.f, v1 = 0.f;
    if (ic0     < CINR) v0 = w[c_WOFF[l] + (oc * CINR + ic0    ) * 9 + s16];
    if (ic0 + 1 < CINR) v1 = w[c_WOFF[l] + (oc * CINR + ic0 + 1) * 9 + s16];
    __half2 h = __floats2half2_rn(v0, v1);
    wp[i] = *reinterpret_cast<uint32_t*>(&h);
}

// Transpose NCHW 3-channel input to NHWC-16 (channels 3..15 zero).
__global__ void __launch_bounds__(256)
xpose_k(const float* __restrict__ in, float* __restrict__ out) {
    const int idx = blockIdx.x * 256 + threadIdx.x;   // (n*1024 + y*32 + x)
    const int n  = idx >> 10;
    const int hw = idx & 1023;
    const float* ib = in + (size_t)n * 3 * 1024 + hw;
    float4 a = make_float4(__ldg(ib), __ldg(ib + 1024), __ldg(ib + 2048), 0.f);
    float4 z = make_float4(0.f, 0.f, 0.f, 0.f);
    float4* ob = (float4*)(out + (size_t)idx * 16);
    ob[0] = a; ob[1] = z; ob[2] = z; ob[3] = z;
}

// ---------------------------------------------------------------------------
// Direct-from-tile tensor-core conv, fp16 MMA (m16n8k16), channel-last fp32
// activations. All layers: ICC=16, K=144, 9 k16-steps, PITCH=72 words.
//  CIN = buffer channels (16/32/64); NCH = CIN/16 chunks.
//  MT = m16-tiles per warp; positions per CTA = 128*MT. MINB = min blocks/SM.
//  MODE 0: plain; 1: relu(bn(in)); 2: +identity prev; 3: +padded/strided prev.
//  WF: also write transformed activation to `fused` (fp32 channel-last).
// ---------------------------------------------------------------------------
template<int CIN, int COUT, int HIN, int STRIDE, int IMGS,
         int MT, int MODE, int CPREV, bool WF, int MINB>
__global__ void __launch_bounds__(256, MINB)
convt_k(const float* __restrict__ in, const uint32_t* __restrict__ wpb,
        float* __restrict__ out, const double* __restrict__ st_in,
        double* __restrict__ st_out, const float* __restrict__ prev,
        float* __restrict__ fused)
{
    constexpr int W     = HIN / STRIDE;
    constexpr int NPOS  = W * W;
    constexpr int PC    = 128 * MT;              // positions per CTA
    constexpr int R     = PC / (W * IMGS);
    constexpr int SPI   = (IMGS == 1) ? (NPOS / PC) : 1;
    constexpr int TH    = (R - 1) * STRIDE + 3;
    constexpr int TW    = HIN + 2;
    constexpr int NCH   = CIN / 16;
    constexpr int NC    = COUT / 8;
    constexpr int TILEW = IMGS * TH * TW * 8;    // words (16 halfs / pixel)
    constexpr int PADF  = (MODE == 3) ? (CIN - CPREV) / 2 : 0;

    extern __shared__ float smf[];
    float*    s_sc = smf;
    float*    s_sh = smf + 64;
    uint32_t* s_a  = (uint32_t*)(smf + 128);
    uint32_t* s_b  = s_a + TILEW;

    const int tid = threadIdx.x, wid = tid >> 5, lane = tid & 31;
    const int g = lane >> 2, t = lane & 3;

    const int img0 = (IMGS == 1) ? (blockIdx.x / SPI) : blockIdx.x * IMGS;
    const int r0   = (IMGS == 1) ? (blockIdx.x % SPI) * R : 0;

    if (MODE >= 1 && tid < CIN) {
        const double cnt = 1024.0 * HIN * HIN;
        double mm = st_in[tid*2]   / cnt;
        double vv = st_in[tid*2+1] / cnt - mm * mm;
        float rs = rsqrtf((float)vv + 1e-5f);
        s_sc[tid] = rs;
        s_sh[tid] = (float)(-mm) * rs;
    }
    if (MODE >= 1) __syncthreads();

    // row-base word offsets into the tile (rows g, g+8, ... per m16 tile)
    int basew[2 * MT];
#pragma unroll
    for (int i = 0; i < 2 * MT; i++) {
        const int p   = wid * (16 * MT) + i * 8 + g;
        const int img = p / (R * W);
        const int rem = p - img * (R * W);
        const int y   = rem / W, x = rem - (rem / W) * W;
        basew[i] = ((img * TH + y * STRIDE) * TW + x * STRIDE) * 8 + 2 * t;
    }

    float acc[MT][NC][4];
#pragma unroll
    for (int mt = 0; mt < MT; mt++)
#pragma unroll
        for (int nc = 0; nc < NC; nc++)
#pragma unroll
            for (int i = 0; i < 4; i++) acc[mt][nc][i] = 0.f;

    for (int ch = 0; ch < NCH; ch++) {
        const int ic0 = ch * 16;
        __syncthreads();

        // ---- stage input tile: 16 channels -> 8 half2 words per pixel ----
        for (int idx = tid; idx < IMGS * TH * TW; idx += 256) {
            const int img = idx / (TH * TW);
            const int rr  = idx - img * (TH * TW);
            const int ty  = rr / TW, tx = rr - (rr / TW) * TW;
            const int yi  = r0 * STRIDE - 1 + ty;
            const int xi  = tx - 1;
            const bool ok = (unsigned)yi < (unsigned)HIN && (unsigned)xi < (unsigned)HIN;
            const int  n  = img0 + img;
            uint32_t* dst = s_a + ((img * TH + ty) * TW + tx) * 8;

            const float* gcl = in + (((size_t)n * HIN + yi) * HIN + xi) * CIN + ic0;
            const float* pcl = nullptr;
            if (MODE == 2)
                pcl = prev + (((size_t)n * HIN + yi) * HIN + xi) * CPREV + ic0;
            if (MODE == 3)
                pcl = prev + (((size_t)n * (2*HIN) + 2*yi) * (2*HIN) + 2*xi) * CPREV;
            float* fcl = nullptr;
            if (WF) fcl = fused + (((size_t)n * HIN + yi) * HIN + xi) * CIN + ic0;

            float v[16];
#pragma unroll
            for (int q = 0; q < 4; q++) {
                float4 f = ok ? *(const float4*)(gcl + q * 4)
                              : make_float4(0.f,0.f,0.f,0.f);
                v[q*4+0] = f.x; v[q*4+1] = f.y; v[q*4+2] = f.z; v[q*4+3] = f.w;
            }
            if (MODE >= 1 && ok) {
#pragma unroll
                for (int q = 0; q < 4; q++) {
                    const float4 sc = *(const float4*)&s_sc[ic0 + q*4];
                    const float4 sh = *(const float4*)&s_sh[ic0 + q*4];
                    v[q*4+0] = fmaf(v[q*4+0], sc.x, sh.x);
                    v[q*4+1] = fmaf(v[q*4+1], sc.y, sh.y);
                    v[q*4+2] = fmaf(v[q*4+2], sc.z, sh.z);
                    v[q*4+3] = fmaf(v[q*4+3], sc.w, sh.w);
                }
                if (MODE == 2) {
#pragma unroll
                    for (int q = 0; q < 4; q++) {
                        const float4 p4 = *(const float4*)(pcl + q * 4);
                        v[q*4+0] += p4.x; v[q*4+1] += p4.y;
                        v[q*4+2] += p4.z; v[q*4+3] += p4.w;
                    }
                }
                if (MODE == 3) {
#pragma unroll
                    for (int h = 0; h < 2; h++) {
                        const int gb = ic0 + 8*h - PADF;
                        if (gb >= 0 && gb + 8 <= CPREV) {
#pragma unroll
                            for (int q = 0; q < 2; q++) {
                                const float4 p4 = *(const float4*)(pcl + gb + q * 4);
                                v[h*8+q*4+0] += p4.x; v[h*8+q*4+1] += p4.y;
                                v[h*8+q*4+2] += p4.z; v[h*8+q*4+3] += p4.w;
                            }
                        }
                    }
                }
#pragma unroll
                for (int q = 0; q < 16; q++) v[q] = fmaxf(v[q], 0.f);
            }
            if (WF && ok) {
#pragma unroll
                for (int q = 0; q < 4; q++)
                    *(float4*)(fcl + q * 4) = make_float4(v[q*4+0], v[q*4+1],
                                                          v[q*4+2], v[q*4+3]);
            }
            // pack: word 2u = pair u = ch(2u,2u+1); word 2u+1 = pair u+4
            uint4* d4 = (uint4*)dst;
            d4[0] = make_uint4(packh(v[0],  v[1]),  packh(v[8],  v[9]),
                               packh(v[2],  v[3]),  packh(v[10], v[11]));
            d4[1] = make_uint4(packh(v[4],  v[5]),  packh(v[12], v[13]),
                               packh(v[6],  v[7]),  packh(v[14], v[15]));
        }

        // ---- stage B: vector copy of pre-packed fp16 weights ----
        {
            const uint4* wb = (const uint4*)(wpb + ch * (COUT * 72));
            uint4* sb4 = (uint4*)s_b;
#pragma unroll 4
            for (int idx = tid; idx < COUT * 72 / 4; idx += 256)
                sb4[idx] = wb[idx];
        }
        __syncthreads();

        // ---- MMA over 9 k16-steps (kpos 0..8) ----
#pragma unroll
        for (int s = 0; s < 9; s++) {
            const int ky  = s / 3, kx = s - (s / 3) * 3;
            const int off = (ky * TW + kx) * 8;
            uint2 Af[2 * MT];
#pragma unroll
            for (int i = 0; i < 2 * MT; i++)
                Af[i] = *(const uint2*)(s_a + basew[i] + off);
#pragma unroll
            for (int nc = 0; nc < NC; nc++) {
                uint2 B = *(const uint2*)(s_b + (nc * 8 + g) * 72 + s * 8 + 2 * t);
#pragma unroll
                for (int mt = 0; mt < MT; mt++)
                    mma_f16(acc[mt][nc], Af[2*mt].x, Af[2*mt+1].x,
                            Af[2*mt].y, Af[2*mt+1].y, B.x, B.y);
            }
        }
    }

    __syncthreads();   // mainloop smem regions free from here
    float* s_st  = smf + 128;          // [PC][COUT]
    float* s_red = s_st + COUT * PC;   // [8 warps][COUT][2]

    // ---- BN stats straight from accumulators ----
#pragma unroll
    for (int nc = 0; nc < NC; nc++) {
        float s0 = 0.f, s1 = 0.f, q0 = 0.f, q1 = 0.f;
#pragma unroll
        for (int mt = 0; mt < MT; mt++) {
            s0 += acc[mt][nc][0] + acc[mt][nc][2];
            s1 += acc[mt][nc][1] + acc[mt][nc][3];
            q0 += acc[mt][nc][0]*acc[mt][nc][0] + acc[mt][nc][2]*acc[mt][nc][2];
            q1 += acc[mt][nc][1]*acc[mt][nc][1] + acc[mt][nc][3]*acc[mt][nc][3];
        }
#pragma unroll
        for (int off = 4; off < 32; off <<= 1) {
            s0 += __shfl_xor_sync(0xffffffffu, s0, off);
            s1 += __shfl_xor_sync(0xffffffffu, s1, off);
            q0 += __shfl_xor_sync(0xffffffffu, q0, off);
            q1 += __shfl_xor_sync(0xffffffffu, q1, off);
        }
        if (lane < 4) {
            const int cb = nc * 8 + 2 * lane;
            s_red[(wid * COUT + cb)     * 2 + 0] = s0;
            s_red[(wid * COUT + cb)     * 2 + 1] = q0;
            s_red[(wid * COUT + cb + 1) * 2 + 0] = s1;
            s_red[(wid * COUT + cb + 1) * 2 + 1] = q1;
        }
    }

    // ---- frags -> smem staging [PC][COUT] (float2 per frag pair) ----
#pragma unroll
    for (int mt = 0; mt < MT; mt++)
#pragma unroll
        for (int nc = 0; nc < NC; nc++) {
            const int cb = nc * 8 + 2 * t;
            const int p0 = wid * (16 * MT) + mt * 16 + g;
            *(float2*)&s_st[p0 * COUT + cb]       = make_float2(acc[mt][nc][0], acc[mt][nc][1]);
            *(float2*)&s_st[(p0 + 8) * COUT + cb] = make_float2(acc[mt][nc][2], acc[mt][nc][3]);
        }
    __syncthreads();

    // coalesced channel-last store (float4)
    for (int idx = tid; idx < COUT * PC / 4; idx += 256) {
        const int c4  = idx % (COUT / 4);
        const int lp  = idx / (COUT / 4);
        const int img = lp / (R * W);
        const int rem = lp - img * (R * W);
        const int y   = r0 + rem / W;
        const int x   = rem - (rem / W) * W;
        const float4 v = *(const float4*)&s_st[lp * COUT + c4 * 4];
        *(float4*)&out[(((size_t)(img0 + img) * W + y) * W + x) * COUT + c4 * 4] = v;
    }

    if (tid < COUT) {
        float s = 0.f, q = 0.f;
#pragma unroll
        for (int w8 = 0; w8 < 8; w8++) {
            s += s_red[(w8 * COUT + tid) * 2 + 0];
            q += s_red[(w8 * COUT + tid) * 2 + 1];
        }
        atomicAdd(&st_out[tid * 2 + 0], (double)s);
        atomicAdd(&st_out[tid * 2 + 1], (double)q);
    }
}

// ---------------------------------------------------------------------------
// Fused final residual + global average pool (8x8) + FC 64->10 (channel-last)
// ---------------------------------------------------------------------------
__global__ void __launch_bounds__(64)
poolfc_k(const float* __restrict__ h2, const double* __restrict__ st,
         const float* __restrict__ prev, const float* __restrict__ Wfc,
         const float* __restrict__ bfc, float* __restrict__ out)
{
    __shared__ float pooled[64];
    const int n = blockIdx.x, t = threadIdx.x;
    const double cnt = 1024.0 * 64.0;
    double m = st[t*2] / cnt;
    double v = st[t*2+1] / cnt - m * m;
    const float sc = rsqrtf((float)v + 1e-5f);
    const float sh = (float)(-m) * sc;
    const float* hp = h2   + (size_t)n * 64 * 64;
    const float* pp = prev + (size_t)n * 64 * 64;
    float s = 0.f;
#pragma unroll
    for (int i = 0; i < 64; i++)
        s += fmaxf(fmaf(hp[i * 64 + t], sc, sh) + pp[i * 64 + t], 0.f);
    pooled[t] = s * (1.f / 64.f);
    __syncthreads();
    if (t < 10) {
        float a = bfc[t];
#pragma unroll
        for (int c = 0; c < 64; c++) a = fmaf(Wfc[t * 64 + c], pooled[c], a);
        out[n * 10 + t] = a;
    }
}

// ---------------------------------------------------------------------------
// Host-side smem size (mirror of kernel constants)
// ---------------------------------------------------------------------------
static constexpr int cm3(int COUT, int HIN, int STRIDE, int IMGS, int MT) {
    int W  = HIN / STRIDE;
    int PC = 128 * MT;
    int R  = PC / (W * IMGS);
    int TH = (R - 1) * STRIDE + 3;
    int TW = HIN + 2;
    int tile = IMGS * TH * TW * 8;
    int p1 = tile + COUT * 72;
    int p2 = COUT * PC + 16 * COUT;
    int m  = (p1 > p2) ? p1 : p2;
    return (128 + m) * 4;
}

extern "C" void kernel_launch(void* const* d_in, const int* in_sizes, int n_in,
                              void* d_out, int out_size)
{
    (void)in_sizes; (void)n_in; (void)out_size;
    const float* x   = (const float*)d_in[0];
    const float* ow  = (const float*)d_in[1];
    const float* P   = (const float*)d_in[2];
    const float* npar= (const float*)d_in[3];
    const float* Wfc = (const float*)d_in[4];
    const float* bfc = (const float*)d_in[5];
    float* y = (float*)d_out;

    float *A, *B, *C, *D, *w; uint32_t* wp; double* st;
    cudaGetSymbolAddress((void**)&A,  g_bufA);
    cudaGetSymbolAddress((void**)&B,  g_bufB);
    cudaGetSymbolAddress((void**)&C,  g_bufC);
    cudaGetSymbolAddress((void**)&D,  g_bufD);
    cudaGetSymbolAddress((void**)&w,  g_w);
    cudaGetSymbolAddress((void**)&wp, g_wp);
    cudaGetSymbolAddress((void**)&st, g_stats);

    #define SETSM(FN, COUT_, HIN_, STRIDE_, IMGS_, MT_) \
        cudaFuncSetAttribute(FN, cudaFuncAttributeMaxDynamicSharedMemorySize, \
                             cm3(COUT_, HIN_, STRIDE_, IMGS_, MT_))

    auto I0  = convt_k<16,16,32,1,1,2,0, 0,false,5>; SETSM(I0, 16,32,1,1,2);
    auto I1  = convt_k<16,16,32,1,1,2,1, 0,true ,5>; SETSM(I1, 16,32,1,1,2);
    auto I2  = convt_k<16,16,32,1,1,2,1, 0,false,5>; SETSM(I2, 16,32,1,1,2);
    auto I3  = convt_k<16,16,32,1,1,2,2,16,true ,4>; SETSM(I3, 16,32,1,1,2);
    auto I4  = convt_k<16,32,32,2,1,2,2,16,true ,4>; SETSM(I4, 32,32,2,1,2);
    auto I5  = convt_k<32,32,16,1,1,2,1, 0,false,4>; SETSM(I5, 32,16,1,1,2);
    auto I6  = convt_k<32,32,16,1,1,2,3,16,true ,4>; SETSM(I6, 32,16,1,1,2);
    auto I7  = convt_k<32,32,16,1,1,2,2,32,true ,4>; SETSM(I7, 32,16,1,1,2);
    auto I8  = convt_k<32,64,16,2,4,2,2,32,true ,2>; SETSM(I8, 64,16,2,4,2);
    auto I9  = convt_k<64,64, 8,1,4,2,1, 0,false,2>; SETSM(I9, 64, 8,1,4,2);
    auto I10 = convt_k<64,64, 8,1,4,2,3,32,true ,2>; SETSM(I10,64, 8,1,4,2);
    auto I11 = convt_k<64,64, 8,1,4,2,2,64,true ,2>; SETSM(I11,64, 8,1,4,2);
    #undef SETSM

    auto ST = [&](int l) { return st + l * 128; };
    auto WL = [&](int l) { return wp + PO_H[l]; };

    zstats_k<<<(19*64*2 + 255)/256, 256>>>(st);
    wbuild_k<<<(D_TOT + 255)/256, 256>>>(ow, P, npar, w);
    wperm_k<<<(WP_TOT + 255)/256, 256>>>(w, wp);
    xpose_k<<<4096, 256>>>(x, D);   // NCHW 3ch -> NHWC-16 (zero padded)

    const int S1 = cm3(16,32,1,1,2);
    const int S3 = cm3(32,32,2,1,2);
    const int S4 = cm3(32,16,1,1,2);
    const int S5 = cm3(64,16,2,4,2);
    const int S6 = cm3(64, 8,1,4,2);

    // layer 0 (channel-last padded input in D)
    I0 <<<4096,256,S1>>>(D, WL(0), A, nullptr, ST(0), nullptr, nullptr);
    // block 1
    I1 <<<4096,256,S1>>>(A, WL(1), B, ST(0),  ST(1), nullptr, C);
    I2 <<<4096,256,S1>>>(B, WL(2), A, ST(1),  ST(2), nullptr, nullptr);
    // block 2
    I3 <<<4096,256,S1>>>(A, WL(3), B, ST(2),  ST(3), C, D);
    I2 <<<4096,256,S1>>>(B, WL(4), C, ST(3),  ST(4), nullptr, nullptr);
    // block 3
    I3 <<<4096,256,S1>>>(C, WL(5), B, ST(4),  ST(5), D, A);
    I2 <<<4096,256,S1>>>(B, WL(6), D, ST(5),  ST(6), nullptr, nullptr);
    // block 4 (16->32, stride 2)
    I4 <<<1024,256,S3>>>(D, WL(7), B, ST(6),  ST(7), A, C);
    I5 <<<1024,256,S4>>>(B, WL(8), A, ST(7),  ST(8), nullptr, nullptr);
    // block 5 (MODE3 pad shortcut, prev 16ch@32)
    I6 <<<1024,256,S4>>>(A, WL(9), B, ST(8),  ST(9), C, D);
    I5 <<<1024,256,S4>>>(B, WL(10),C, ST(9),  ST(10),nullptr, nullptr);
    // block 6
    I7 <<<1024,256,S4>>>(C, WL(11),B, ST(10), ST(11),D, A);
    I5 <<<1024,256,S4>>>(B, WL(12),D, ST(11), ST(12),nullptr, nullptr);
    // block 7 (32->64, stride 2)
    I8 <<< 256,256,S5>>>(D, WL(13),B, ST(12), ST(13),A, C);
    I9 <<< 256,256,S6>>>(B, WL(14),A, ST(13), ST(14),nullptr, nullptr);
    // block 8 (MODE3 pad shortcut, prev 32ch@16)
    I10<<< 256,256,S6>>>(A, WL(15),B, ST(14), ST(15),C, D);
    I9 <<< 256,256,S6>>>(B, WL(16),C, ST(15), ST(16),nullptr, nullptr);
    // block 9
    I11<<< 256,256,S6>>>(C, WL(17),B, ST(16), ST(17),D, A);
    I9 <<< 256,256,S6>>>(B, WL(18),D, ST(17), ST(18),nullptr, nullptr);
    // fused final residual + pool + fc
    poolfc_k<<<NB,64>>>(D, ST(18), A, Wfc, bfc, y);
}

// round 17
// speedup vs baseline: 1.4489x; 1.1692x over previous
#include <cuda_runtime.h>
#include <cuda_fp16.h>
#include <cstdint>
#include <cstdio>

// ---------------------------------------------------------------------------
// Problem constants
// ---------------------------------------------------------------------------
#define NB 1024
static const int D_TOT = 267696;

// fp16-packed permuted weight buffer, word offsets per layer.
// All layers use ICC=16 (K=144, 9 k16-steps), PITCH = 72 words (144 halfs).
static const int PO_H[19] = {0,1152,2304,3456,4608,5760,6912,8064,10368,14976,
                             19584,24192,28800,33408,42624,61056,79488,97920,116352};
#define WP_TOT 134784

__constant__ int c_PO[19]   = {0,1152,2304,3456,4608,5760,6912,8064,10368,14976,
                               19584,24192,28800,33408,42624,61056,79488,97920,116352};
__constant__ int c_WOFF[19] = {0,432,2736,5040,7344,9648,11952,14256,18864,28080,
                               37296,46512,55728,64944,83376,120240,157104,193968,230832};
__constant__ int c_LCIN[19]  = {3,16,16,16,16,16,16,16,32,32,32,32,32,32,64,64,64,64,64};
__constant__ int c_LCOUT[19] = {16,16,16,16,16,16,16,32,32,32,32,32,32,64,64,64,64,64,64};

// ---------------------------------------------------------------------------
// Device scratch (activations now fp16 NHWC)
// ---------------------------------------------------------------------------
#define BUF_ELEMS (1024*16*32*32)
__device__ __half   g_bufA[BUF_ELEMS];
__device__ __half   g_bufB[BUF_ELEMS];
__device__ __half   g_bufC[BUF_ELEMS];
__device__ __half   g_bufD[BUF_ELEMS];
__device__ float    g_w[267696];       // natural per-layer layout: [oc][ic][3][3]
__device__ uint32_t g_wp[WP_TOT];      // fp16-packed permuted weights
__device__ double   g_stats[19*64*2];  // per layer, per channel: sum, sumsq

// ---------------------------------------------------------------------------
// helpers
// ---------------------------------------------------------------------------
__device__ __forceinline__ uint32_t packh(float a, float b) {
    __half2 h = __floats2half2_rn(a, b);
    return *reinterpret_cast<uint32_t*>(&h);
}
__device__ __forceinline__ float2 unph(uint32_t w) {
    return __half22float2(*reinterpret_cast<__half2*>(&w));
}
__device__ __forceinline__ void mma_f16(float c[4],
                                        uint32_t a0, uint32_t a1, uint32_t a2, uint32_t a3,
                                        uint32_t b0, uint32_t b1) {
    asm volatile(
        "mma.sync.aligned.m16n8k16.row.col.f32.f16.f16.f32 "
        "{%0,%1,%2,%3}, {%4,%5,%6,%7}, {%8,%9}, {%0,%1,%2,%3};"
        : "+f"(c[0]), "+f"(c[1]), "+f"(c[2]), "+f"(c[3])
        : "r"(a0), "r"(a1), "r"(a2), "r"(a3), "r"(b0), "r"(b1));
}

// ---------------------------------------------------------------------------
__global__ void zstats_k(double* __restrict__ st) {
    int i = blockIdx.x * blockDim.x + threadIdx.x;
    if (i < 19*64*2) st[i] = 0.0;
}

__global__ void wbuild_k(const float* __restrict__ ow, const float* __restrict__ P,
                         const float* __restrict__ npar, float* __restrict__ wt) {
    __shared__ float s_np[40];
    if (threadIdx.x < 40) s_np[threadIdx.x] = npar[threadIdx.x];
    __syncthreads();
    int d = blockIdx.x * blockDim.x + threadIdx.x;
    if (d >= D_TOT) return;
    float a = ow[d];
#pragma unroll
    for (int j = 0; j < 40; j++)
        a = fmaf(s_np[j], P[(size_t)j * D_TOT + d], a);
    wt[d] = a;
}

// Permute + fp16-pack weights into the exact smem image the conv consumes.
__global__ void wperm_k(const float* __restrict__ w, uint32_t* __restrict__ wp) {
    int i = blockIdx.x * blockDim.x + threadIdx.x;
    if (i >= WP_TOT) return;
    int l = 18;
    while (l > 0 && i < c_PO[l]) l--;
    const int r     = i - c_PO[l];
    const int CINR  = c_LCIN[l];
    const int COUT  = c_LCOUT[l];
    const int cs    = COUT * 72;
    const int ch    = r / cs;
    const int r2    = r - ch * cs;
    const int oc    = r2 / 72;
    const int wd    = r2 - oc * 72;
    const int s16   = wd >> 3;            // kpos 0..8
    const int j     = wd & 7;
    const int p     = (j & 1) ? (j >> 1) + 4 : (j >> 1);
    const int ic0   = ch * 16 + 2 * p;
    float v0 = 0.f, v1 = 0.f;
    if (ic0     < CINR) v0 = w[c_WOFF[l] + (oc * CINR + ic0    ) * 9 + s16];
    if (ic0 + 1 < CINR) v1 = w[c_WOFF[l] + (oc * CINR + ic0 + 1) * 9 + s16];
    __half2 h = __floats2half2_rn(v0, v1);
    wp[i] = *reinterpret_cast<uint32_t*>(&h);
}

// Transpose NCHW 3-channel fp32 input to fp16 NHWC-16 (channels 3..15 zero).
__global__ void __launch_bounds__(256)
xpose_k(const float* __restrict__ in, __half* __restrict__ out) {
    const int idx = blockIdx.x * 256 + threadIdx.x;   // (n*1024 + y*32 + x)
    const int n  = idx >> 10;
    const int hw = idx & 1023;
    const float* ib = in + (size_t)n * 3 * 1024 + hw;
    uint4 a = make_uint4(packh(__ldg(ib), __ldg(ib + 1024)),
                         packh(__ldg(ib + 2048), 0.f), 0u, 0u);
    uint4 z = make_uint4(0u, 0u, 0u, 0u);
    uint4* ob = (uint4*)(out + (size_t)idx * 16);
    ob[0] = a;
    ob[1] = z;
}

// ---------------------------------------------------------------------------
// Direct-from-tile tensor-core conv, fp16 MMA (m16n8k16), fp16 NHWC
// activations. All layers: ICC=16, K=144, 9 k16-steps, PITCH=72 words.
//  MODE 0: plain (pure word permute, no cvt); 1: relu(bn(in));
//  2: +identity prev; 3: +padded/strided prev.
//  WF: also write transformed activation to `fused` (fp16 NHWC).
// ---------------------------------------------------------------------------
template<int CIN, int COUT, int HIN, int STRIDE, int IMGS,
         int MT, int MODE, int CPREV, bool WF, int MINB>
__global__ void __launch_bounds__(256, MINB)
convt_k(const __half* __restrict__ in, const uint32_t* __restrict__ wpb,
        __half* __restrict__ out, const double* __restrict__ st_in,
        double* __restrict__ st_out, const __half* __restrict__ prev,
        __half* __restrict__ fused)
{
    constexpr int W     = HIN / STRIDE;
    constexpr int NPOS  = W * W;
    constexpr int PC    = 128 * MT;              // positions per CTA
    constexpr int R     = PC / (W * IMGS);
    constexpr int SPI   = (IMGS == 1) ? (NPOS / PC) : 1;
    constexpr int TH    = (R - 1) * STRIDE + 3;
    constexpr int TW    = HIN + 2;
    constexpr int NCH   = CIN / 16;
    constexpr int NC    = COUT / 8;
    constexpr int TILEW = IMGS * TH * TW * 8;    // words (16 halfs / pixel)
    constexpr int PADF  = (MODE == 3) ? (CIN - CPREV) / 2 : 0;

    extern __shared__ float smf[];
    float*    s_sc = smf;
    float*    s_sh = smf + 64;
    uint32_t* s_a  = (uint32_t*)(smf + 128);
    uint32_t* s_b  = s_a + TILEW;

    const int tid = threadIdx.x, wid = tid >> 5, lane = tid & 31;
    const int g = lane >> 2, t = lane & 3;

    const int img0 = (IMGS == 1) ? (blockIdx.x / SPI) : blockIdx.x * IMGS;
    const int r0   = (IMGS == 1) ? (blockIdx.x % SPI) * R : 0;

    if (MODE >= 1 && tid < CIN) {
        const double cnt = 1024.0 * HIN * HIN;
        double mm = st_in[tid*2]   / cnt;
        double vv = st_in[tid*2+1] / cnt - mm * mm;
        float rs = rsqrtf((float)vv + 1e-5f);
        s_sc[tid] = rs;
        s_sh[tid] = (float)(-mm) * rs;
    }
    if (MODE >= 1) __syncthreads();

    // row-base word offsets into the tile (rows g, g+8, ... per m16 tile)
    int basew[2 * MT];
#pragma unroll
    for (int i = 0; i < 2 * MT; i++) {
        const int p   = wid * (16 * MT) + i * 8 + g;
        const int img = p / (R * W);
        const int rem = p - img * (R * W);
        const int y   = rem / W, x = rem - (rem / W) * W;
        basew[i] = ((img * TH + y * STRIDE) * TW + x * STRIDE) * 8 + 2 * t;
    }

    float acc[MT][NC][4];
#pragma unroll
    for (int mt = 0; mt < MT; mt++)
#pragma unroll
        for (int nc = 0; nc < NC; nc++)
#pragma unroll
            for (int i = 0; i < 4; i++) acc[mt][nc][i] = 0.f;

    for (int ch = 0; ch < NCH; ch++) {
        const int ic0 = ch * 16;
        __syncthreads();

        // ---- stage input tile: fp16 in, 8 half2 words per pixel ----
        for (int idx = tid; idx < IMGS * TH * TW; idx += 256) {
            const int img = idx / (TH * TW);
            const int rr  = idx - img * (TH * TW);
            const int ty  = rr / TW, tx = rr - (rr / TW) * TW;
            const int yi  = r0 * STRIDE - 1 + ty;
            const int xi  = tx - 1;
            const bool ok = (unsigned)yi < (unsigned)HIN && (unsigned)xi < (unsigned)HIN;
            const int  n  = img0 + img;
            uint32_t* dst = s_a + ((img * TH + ty) * TW + tx) * 8;

            const __half* gcl = in + (((size_t)n * HIN + yi) * HIN + xi) * CIN + ic0;
            const uint4 zz = make_uint4(0u,0u,0u,0u);
            uint4 raw0 = ok ? *(const uint4*)gcl       : zz;   // pairs 0..3
            uint4 raw1 = ok ? *(const uint4*)(gcl + 8) : zz;   // pairs 4..7

            uint4* d4 = (uint4*)dst;
            if (MODE == 0) {
                // pure permute: [p0,p4,p1,p5] [p2,p6,p3,p7]
                d4[0] = make_uint4(raw0.x, raw1.x, raw0.y, raw1.y);
                d4[1] = make_uint4(raw0.z, raw1.z, raw0.w, raw1.w);
            } else {
                float v[16];
                {
                    float2 f;
                    f = unph(raw0.x); v[0]=f.x;  v[1]=f.y;
                    f = unph(raw0.y); v[2]=f.x;  v[3]=f.y;
                    f = unph(raw0.z); v[4]=f.x;  v[5]=f.y;
                    f = unph(raw0.w); v[6]=f.x;  v[7]=f.y;
                    f = unph(raw1.x); v[8]=f.x;  v[9]=f.y;
                    f = unph(raw1.y); v[10]=f.x; v[11]=f.y;
                    f = unph(raw1.z); v[12]=f.x; v[13]=f.y;
                    f = unph(raw1.w); v[14]=f.x; v[15]=f.y;
                }
                if (ok) {
#pragma unroll
                    for (int q = 0; q < 4; q++) {
                        const float4 sc = *(const float4*)&s_sc[ic0 + q*4];
                        const float4 sh = *(const float4*)&s_sh[ic0 + q*4];
                        v[q*4+0] = fmaf(v[q*4+0], sc.x, sh.x);
                        v[q*4+1] = fmaf(v[q*4+1], sc.y, sh.y);
                        v[q*4+2] = fmaf(v[q*4+2], sc.z, sh.z);
                        v[q*4+3] = fmaf(v[q*4+3], sc.w, sh.w);
                    }
                    if (MODE == 2) {
                        const __half* pcl = prev +
                            (((size_t)n * HIN + yi) * HIN + xi) * CPREV + ic0;
                        uint4 p0 = *(const uint4*)pcl;
                        uint4 p1 = *(const uint4*)(pcl + 8);
                        float2 f;
                        f = unph(p0.x); v[0]+=f.x;  v[1]+=f.y;
                        f = unph(p0.y); v[2]+=f.x;  v[3]+=f.y;
                        f = unph(p0.z); v[4]+=f.x;  v[5]+=f.y;
                        f = unph(p0.w); v[6]+=f.x;  v[7]+=f.y;
                        f = unph(p1.x); v[8]+=f.x;  v[9]+=f.y;
                        f = unph(p1.y); v[10]+=f.x; v[11]+=f.y;
                        f = unph(p1.z); v[12]+=f.x; v[13]+=f.y;
                        f = unph(p1.w); v[14]+=f.x; v[15]+=f.y;
                    }
                    if (MODE == 3) {
                        const __half* pcl = prev +
                            (((size_t)n * (2*HIN) + 2*yi) * (2*HIN) + 2*xi) * CPREV;
#pragma unroll
                        for (int h = 0; h < 2; h++) {
                            const int gb = ic0 + 8*h - PADF;
                            if (gb >= 0 && gb + 8 <= CPREV) {
                                uint4 p4 = *(const uint4*)(pcl + gb);
                                float2 f;
                                f = unph(p4.x); v[h*8+0]+=f.x; v[h*8+1]+=f.y;
                                f = unph(p4.y); v[h*8+2]+=f.x; v[h*8+3]+=f.y;
                                f = unph(p4.z); v[h*8+4]+=f.x; v[h*8+5]+=f.y;
                                f = unph(p4.w); v[h*8+6]+=f.x; v[h*8+7]+=f.y;
                            }
                        }
                    }
#pragma unroll
                    for (int q = 0; q < 16; q++) v[q] = fmaxf(v[q], 0.f);
                }
                uint32_t pw[8];
#pragma unroll
                for (int p = 0; p < 8; p++) pw[p] = packh(v[2*p], v[2*p+1]);
                if (WF && ok) {
                    __half* fcl = fused +
                        (((size_t)n * HIN + yi) * HIN + xi) * CIN + ic0;
                    uint4* f4 = (uint4*)fcl;
                    f4[0] = make_uint4(pw[0], pw[1], pw[2], pw[3]);
                    f4[1] = make_uint4(pw[4], pw[5], pw[6], pw[7]);
                }
                // fragment order: [p0,p4,p1,p5] [p2,p6,p3,p7]
                d4[0] = make_uint4(pw[0], pw[4], pw[1], pw[5]);
                d4[1] = make_uint4(pw[2], pw[6], pw[3], pw[7]);
            }
        }

        // ---- stage B: vector copy of pre-packed fp16 weights ----
        {
            const uint4* wb = (const uint4*)(wpb + ch * (COUT * 72));
            uint4* sb4 = (uint4*)s_b;
#pragma unroll 4
            for (int idx = tid; idx < COUT * 72 / 4; idx += 256)
                sb4[idx] = wb[idx];
        }
        __syncthreads();

        // ---- MMA over 9 k16-steps (kpos 0..8) ----
#pragma unroll
        for (int s = 0; s < 9; s++) {
            const int ky  = s / 3, kx = s - (s / 3) * 3;
            const int off = (ky * TW + kx) * 8;
            uint2 Af[2 * MT];
#pragma unroll
            for (int i = 0; i < 2 * MT; i++)
                Af[i] = *(const uint2*)(s_a + basew[i] + off);
#pragma unroll
            for (int nc = 0; nc < NC; nc++) {
                uint2 B = *(const uint2*)(s_b + (nc * 8 + g) * 72 + s * 8 + 2 * t);
#pragma unroll
                for (int mt = 0; mt < MT; mt++)
                    mma_f16(acc[mt][nc], Af[2*mt].x, Af[2*mt+1].x,
                            Af[2*mt].y, Af[2*mt+1].y, B.x, B.y);
            }
        }
    }

    __syncthreads();   // mainloop smem regions free from here
    __half* s_st  = (__half*)(smf + 128);            // [PC][COUT] fp16
    float*  s_red = (float*)(s_st + COUT * PC);      // [8 warps][COUT][2]

    // ---- BN stats straight from accumulators (fp32) ----
#pragma unroll
    for (int nc = 0; nc < NC; nc++) {
        float s0 = 0.f, s1 = 0.f, q0 = 0.f, q1 = 0.f;
#pragma unroll
        for (int mt = 0; mt < MT; mt++) {
            s0 += acc[mt][nc][0] + acc[mt][nc][2];
            s1 += acc[mt][nc][1] + acc[mt][nc][3];
            q0 += acc[mt][nc][0]*acc[mt][nc][0] + acc[mt][nc][2]*acc[mt][nc][2];
            q1 += acc[mt][nc][1]*acc[mt][nc][1] + acc[mt][nc][3]*acc[mt][nc][3];
        }
#pragma unroll
        for (int off = 4; off < 32; off <<= 1) {
            s0 += __shfl_xor_sync(0xffffffffu, s0, off);
            s1 += __shfl_xor_sync(0xffffffffu, s1, off);
            q0 += __shfl_xor_sync(0xffffffffu, q0, off);
            q1 += __shfl_xor_sync(0xffffffffu, q1, off);
        }
        if (lane < 4) {
            const int cb = nc * 8 + 2 * lane;
            s_red[(wid * COUT + cb)     * 2 + 0] = s0;
            s_red[(wid * COUT + cb)     * 2 + 1] = q0;
            s_red[(wid * COUT + cb + 1) * 2 + 0] = s1;
            s_red[(wid * COUT + cb + 1) * 2 + 1] = q1;
        }
    }

    // ---- frags -> fp16 smem staging [PC][COUT] ----
#pragma unroll
    for (int mt = 0; mt < MT; mt++)
#pragma unroll
        for (int nc = 0; nc < NC; nc++) {
            const int cb = nc * 8 + 2 * t;
            const int p0 = wid * (16 * MT) + mt * 16 + g;
            *(uint32_t*)&s_st[p0 * COUT + cb] =
                packh(acc[mt][nc][0], acc[mt][nc][1]);
            *(uint32_t*)&s_st[(p0 + 8) * COUT + cb] =
                packh(acc[mt][nc][2], acc[mt][nc][3]);
        }
    __syncthreads();

    // coalesced fp16 channel-last store (uint4 = 8 halfs)
    for (int idx = tid; idx < COUT * PC / 8; idx += 256) {
        const int c8  = idx % (COUT / 8);
        const int lp  = idx / (COUT / 8);
        const int img = lp / (R * W);
        const int rem = lp - img * (R * W);
        const int y   = r0 + rem / W;
        const int x   = rem - (rem / W) * W;
        const uint4 v = *(const uint4*)&s_st[lp * COUT + c8 * 8];
        *(uint4*)&out[(((size_t)(img0 + img) * W + y) * W + x) * COUT + c8 * 8] = v;
    }

    if (tid < COUT) {
        float s = 0.f, q = 0.f;
#pragma unroll
        for (int w8 = 0; w8 < 8; w8++) {
            s += s_red[(w8 * COUT + tid) * 2 + 0];
            q += s_red[(w8 * COUT + tid) * 2 + 1];
        }
        atomicAdd(&st_out[tid * 2 + 0], (double)s);
        atomicAdd(&st_out[tid * 2 + 1], (double)q);
    }
}

// ---------------------------------------------------------------------------
// Fused final residual + global average pool (8x8) + FC 64->10 (fp16 NHWC in)
// ---------------------------------------------------------------------------
__global__ void __launch_bounds__(64)
poolfc_k(const __half* __restrict__ h2, const double* __restrict__ st,
         const __half* __restrict__ prev, const float* __restrict__ Wfc,
         const float* __restrict__ bfc, float* __restrict__ out)
{
    __shared__ float pooled[64];
    const int n = blockIdx.x, t = threadIdx.x;
    const double cnt = 1024.0 * 64.0;
    double m = st[t*2] / cnt;
    double v = st[t*2+1] / cnt - m * m;
    const float sc = rsqrtf((float)v + 1e-5f);
    const float sh = (float)(-m) * sc;
    const __half* hp = h2   + (size_t)n * 64 * 64;
    const __half* pp = prev + (size_t)n * 64 * 64;
    float s = 0.f;
#pragma unroll
    for (int i = 0; i < 64; i++)
        s += fmaxf(fmaf(__half2float(hp[i * 64 + t]), sc, sh)
                   + __half2float(pp[i * 64 + t]), 0.f);
    pooled[t] = s * (1.f / 64.f);
    __syncthreads();
    if (t < 10) {
        float a = bfc[t];
#pragma unroll
        for (int c = 0; c < 64; c++) a = fmaf(Wfc[t * 64 + c], pooled[c], a);
        out[n * 10 + t] = a;
    }
}

// ---------------------------------------------------------------------------
// Host-side smem size (mirror of kernel constants; sizes in bytes)
// ---------------------------------------------------------------------------
static constexpr int cm3(int COUT, int HIN, int STRIDE, int IMGS, int MT) {
    int W  = HIN / STRIDE;
    int PC = 128 * MT;
    int R  = PC / (W * IMGS);
    int TH = (R - 1) * STRIDE + 3;
    int TW = HIN + 2;
    int tileB = (IMGS * TH * TW * 8 + COUT * 72) * 4;     // mainloop words
    int epiB  = COUT * PC * 2 + 16 * COUT * 4;            // fp16 st + red
    int m = (tileB > epiB) ? tileB : epiB;
    return 128 * 4 + m;
}

extern "C" void kernel_launch(void* const* d_in, const int* in_sizes, int n_in,
                              void* d_out, int out_size)
{
    (void)in_sizes; (void)n_in; (void)out_size;
    const float* x   = (const float*)d_in[0];
    const float* ow  = (const float*)d_in[1];
    const float* P   = (const float*)d_in[2];
    const float* npar= (const float*)d_in[3];
    const float* Wfc = (const float*)d_in[4];
    const float* bfc = (const float*)d_in[5];
    float* y = (float*)d_out;

    __half *A, *B, *C, *D; float* w; uint32_t* wp; double* st;
    cudaGetSymbolAddress((void**)&A,  g_bufA);
    cudaGetSymbolAddress((void**)&B,  g_bufB);
    cudaGetSymbolAddress((void**)&C,  g_bufC);
    cudaGetSymbolAddress((void**)&D,  g_bufD);
    cudaGetSymbolAddress((void**)&w,  g_w);
    cudaGetSymbolAddress((void**)&wp, g_wp);
    cudaGetSymbolAddress((void**)&st, g_stats);

    #define SETSM(FN, COUT_, HIN_, STRIDE_, IMGS_, MT_) \
        cudaFuncSetAttribute(FN, cudaFuncAttributeMaxDynamicSharedMemorySize, \
                             cm3(COUT_, HIN_, STRIDE_, IMGS_, MT_))

    auto I0  = convt_k<16,16,32,1,1,2,0, 0,false,5>; SETSM(I0, 16,32,1,1,2);
    auto I1  = convt_k<16,16,32,1,1,2,1, 0,true ,5>; SETSM(I1, 16,32,1,1,2);
    auto I2  = convt_k<16,16,32,1,1,2,1, 0,false,5>; SETSM(I2, 16,32,1,1,2);
    auto I3  = convt_k<16,16,32,1,1,2,2,16,true ,4>; SETSM(I3, 16,32,1,1,2);
    auto I4  = convt_k<16,32,32,2,1,2,2,16,true ,4>; SETSM(I4, 32,32,2,1,2);
    auto I5  = convt_k<32,32,16,1,1,2,1, 0,false,4>; SETSM(I5, 32,16,1,1,2);
    auto I6  = convt_k<32,32,16,1,1,2,3,16,true ,4>; SETSM(I6, 32,16,1,1,2);
    auto I7  = convt_k<32,32,16,1,1,2,2,32,true ,4>; SETSM(I7, 32,16,1,1,2);
    auto I8  = convt_k<32,64,16,2,4,2,2,32,true ,2>; SETSM(I8, 64,16,2,4,2);
    auto I9  = convt_k<64,64, 8,1,4,2,1, 0,false,2>; SETSM(I9, 64, 8,1,4,2);
    auto I10 = convt_k<64,64, 8,1,4,2,3,32,true ,2>; SETSM(I10,64, 8,1,4,2);
    auto I11 = convt_k<64,64, 8,1,4,2,2,64,true ,2>; SETSM(I11,64, 8,1,4,2);
    #undef SETSM

    auto ST = [&](int l) { return st + l * 128; };
    auto WL = [&](int l) { return wp + PO_H[l]; };

    zstats_k<<<(19*64*2 + 255)/256, 256>>>(st);
    wbuild_k<<<(D_TOT + 255)/256, 256>>>(ow, P, npar, w);
    wperm_k<<<(WP_TOT + 255)/256, 256>>>(w, wp);
    xpose_k<<<4096, 256>>>(x, D);   // NCHW 3ch fp32 -> fp16 NHWC-16

    const int S1 = cm3(16,32,1,1,2);
    const int S3 = cm3(32,32,2,1,2);
    const int S4 = cm3(32,16,1,1,2);
    const int S5 = cm3(64,16,2,4,2);
    const int S6 = cm3(64, 8,1,4,2);

    // layer 0 (fp16 NHWC padded input in D)
    I0 <<<4096,256,S1>>>(D, WL(0), A, nullptr, ST(0), nullptr, nullptr);
    // block 1
    I1 <<<4096,256,S1>>>(A, WL(1), B, ST(0),  ST(1), nullptr, C);
    I2 <<<4096,256,S1>>>(B, WL(2), A, ST(1),  ST(2), nullptr, nullptr);
    // block 2
    I3 <<<4096,256,S1>>>(A, WL(3), B, ST(2),  ST(3), C, D);
    I2 <<<4096,256,S1>>>(B, WL(4), C, ST(3),  ST(4), nullptr, nullptr);
    // block 3
    I3 <<<4096,256,S1>>>(C, WL(5), B, ST(4),  ST(5), D, A);
    I2 <<<4096,256,S1>>>(B, WL(6), D, ST(5),  ST(6), nullptr, nullptr);
    // block 4 (16->32, stride 2)
    I4 <<<1024,256,S3>>>(D, WL(7), B, ST(6),  ST(7), A, C);
    I5 <<<1024,256,S4>>>(B, WL(8), A, ST(7),  ST(8), nullptr, nullptr);
    // block 5 (MODE3 pad shortcut, prev 16ch@32)
    I6 <<<1024,256,S4>>>(A, WL(9), B, ST(8),  ST(9), C, D);
    I5 <<<1024,256,S4>>>(B, WL(10),C, ST(9),  ST(10),nullptr, nullptr);
    // block 6
    I7 <<<1024,256,S4>>>(C, WL(11),B, ST(10), ST(11),D, A);
    I5 <<<1024,256,S4>>>(B, WL(12),D, ST(11), ST(12),nullptr, nullptr);
    // block 7 (32->64, stride 2)
    I8 <<< 256,256,S5>>>(D, WL(13),B, ST(12), ST(13),A, C);
    I9 <<< 256,256,S6>>>(B, WL(14),A, ST(13), ST(14),nullptr, nullptr);
    // block 8 (MODE3 pad shortcut, prev 32ch@16)
    I10<<< 256,256,S6>>>(A, WL(15),B, ST(14), ST(15),C, D);
    I9 <<< 256,256,S6>>>(B, WL(16),C, ST(15), ST(16),nullptr, nullptr);
    // block 9
    I11<<< 256,256,S6>>>(C, WL(17),B, ST(16), ST(17),D, A);
    I9 <<< 256,256,S6>>>(B, WL(18),D, ST(17), ST(18),nullptr, nullptr);
    // fused final residual + pool + fc
    poolfc_k<<<NB,64>>>(D, ST(18), A, Wfc, bfc, y);
}